// round 12
// baseline (speedup 1.0000x reference)
#include <cuda_runtime.h>
#include <math.h>

#define LSEQ 2048
#define DMODEL 512
#define NH 8
#define HD 64
#define NFFT 4096
#define EPSF 1e-5f
#define NCHUNK 32
#define TCH 64

typedef unsigned long long u64;

// ---------------- scratch (device globals; no runtime allocation) ----------------
__device__ float g_q[LSEQ * DMODEL];
__device__ float g_k[LSEQ * DMODEL];
__device__ float g_v[LSEQ * DMODEL];
__device__ float g_filt[LSEQ * DMODEL];
__device__ float g_kf[LSEQ * DMODEL];
__device__ float g_vf[LSEQ * DMODEL];
__device__ float g_gate[NH * LSEQ];
__device__ float g_S[NH * NCHUNK * HD * HD];
__device__ float g_Spre[NH * NCHUNK * HD * HD];
__device__ float g_Gpre[NH * NCHUNK];
__device__ float g_sraw[LSEQ * DMODEL];
__device__ float2 g_Ff[(DMODEL / 2) * NFFT];   // packed filter spectra (2 channels/FFT)

// ---------------- packed f32x2 helpers (sm_103a FFMA2 path) ----------------
__device__ __forceinline__ u64 pk2(float v) {
    u64 r; asm("mov.b64 %0, {%1, %1};" : "=l"(r) : "f"(v)); return r;
}
__device__ __forceinline__ void upk2(u64 v, float& lo, float& hi) {
    asm("mov.b64 {%0, %1}, %2;" : "=f"(lo), "=f"(hi) : "l"(v));
}
__device__ __forceinline__ u64 ffma2(u64 a, u64 b, u64 c) {
    u64 d; asm("fma.rn.f32x2 %0, %1, %2, %3;" : "=l"(d) : "l"(a), "l"(b), "l"(c)); return d;
}

// ---------------- double-buffered GEMM body: C[m,n] = sum_k A[m,k]*W[n,k] + bias[n] -------
// 64x64 tile, 256 threads, 4x4 acc (packed f32x2), K=N=512 fixed.
// l2n != 0: L2-normalize each 64-wide output row segment (N-tile == one head).
__device__ __forceinline__ void gemm_body(const float* __restrict__ A, const float* __restrict__ W,
                                          const float* __restrict__ bias, float* __restrict__ C,
                                          int l2n) {
    __shared__ __align__(16) float As[2][16][68];
    __shared__ __align__(16) float Ws[2][16][68];
    int tid = threadIdx.x;                 // 256 threads
    int bm = blockIdx.y * 64, bn = blockIdx.x * 64;
    int row = tid >> 2, kc = (tid & 3) << 2;
    int tx = tid & 15, ty = tid >> 4;
    const float* Ap = A + (size_t)(bm + row) * DMODEL + kc;
    const float* Wp = W + (size_t)(bn + row) * DMODEL + kc;

    u64 acc2[4][2];
#pragma unroll
    for (int i = 0; i < 4; i++) { acc2[i][0] = 0ull; acc2[i][1] = 0ull; }

    // preload tile 0
    {
        float4 a4 = *reinterpret_cast<const float4*>(Ap);
        float4 w4 = *reinterpret_cast<const float4*>(Wp);
        As[0][kc + 0][row] = a4.x; As[0][kc + 1][row] = a4.y; As[0][kc + 2][row] = a4.z; As[0][kc + 3][row] = a4.w;
        Ws[0][kc + 0][row] = w4.x; Ws[0][kc + 1][row] = w4.y; Ws[0][kc + 2][row] = w4.z; Ws[0][kc + 3][row] = w4.w;
    }
    __syncthreads();

    int buf = 0;
    for (int k0 = 16; k0 <= DMODEL; k0 += 16) {
        float4 a4n, w4n;
        bool more = (k0 < DMODEL);
        if (more) {
            a4n = *reinterpret_cast<const float4*>(Ap + k0);
            w4n = *reinterpret_cast<const float4*>(Wp + k0);
        }
#pragma unroll
        for (int kk = 0; kk < 16; kk++) {
            const u64* bp = reinterpret_cast<const u64*>(&Ws[buf][kk][tx * 4]);
            u64 b0 = bp[0], b1 = bp[1];
#pragma unroll
            for (int i = 0; i < 4; i++) {
                u64 ap = pk2(As[buf][kk][ty * 4 + i]);
                acc2[i][0] = ffma2(ap, b0, acc2[i][0]);
                acc2[i][1] = ffma2(ap, b1, acc2[i][1]);
            }
        }
        if (more) {
            int nb = buf ^ 1;
            As[nb][kc + 0][row] = a4n.x; As[nb][kc + 1][row] = a4n.y; As[nb][kc + 2][row] = a4n.z; As[nb][kc + 3][row] = a4n.w;
            Ws[nb][kc + 0][row] = w4n.x; Ws[nb][kc + 1][row] = w4n.y; Ws[nb][kc + 2][row] = w4n.z; Ws[nb][kc + 3][row] = w4n.w;
            __syncthreads();
        }
        buf ^= 1;
    }
    float4 bb = *reinterpret_cast<const float4*>(bias + bn + tx * 4);
#pragma unroll
    for (int i = 0; i < 4; i++) {
        float c0, c1, c2, c3;
        upk2(acc2[i][0], c0, c1);
        upk2(acc2[i][1], c2, c3);
        c0 += bb.x; c1 += bb.y; c2 += bb.z; c3 += bb.w;
        if (l2n) {
            float ss = c0 * c0 + c1 * c1 + c2 * c2 + c3 * c3;
            ss += __shfl_xor_sync(0xffffffffu, ss, 1);
            ss += __shfl_xor_sync(0xffffffffu, ss, 2);
            ss += __shfl_xor_sync(0xffffffffu, ss, 4);
            ss += __shfl_xor_sync(0xffffffffu, ss, 8);
            float inv = 1.f / fmaxf(sqrtf(ss), EPSF);
            c0 *= inv; c1 *= inv; c2 *= inv; c3 *= inv;
        }
        *reinterpret_cast<float4*>(C + (size_t)(bm + ty * 4 + i) * DMODEL + bn + tx * 4)
            = make_float4(c0, c1, c2, c3);
    }
}

// fused Q/K/V/filter projections: blockIdx.z selects the GEMM (1024 blocks total)
__global__ __launch_bounds__(256) void gemm4_kernel(
    const float* __restrict__ x, const float* __restrict__ sb,
    const float* __restrict__ Wq, const float* __restrict__ Wk,
    const float* __restrict__ Wv, const float* __restrict__ Wt,
    const float* __restrict__ bq, const float* __restrict__ bk,
    const float* __restrict__ bv, const float* __restrict__ bt) {
    int z = blockIdx.z;
    const float* A = (z == 3) ? sb : x;
    const float* W = (z == 0) ? Wq : (z == 1) ? Wk : (z == 2) ? Wv : Wt;
    const float* b = (z == 0) ? bq : (z == 1) ? bk : (z == 2) ? bv : bt;
    float* C = (z == 0) ? g_q : (z == 1) ? g_k : (z == 2) ? g_v : g_filt;
    gemm_body(A, W, b, C, (z == 1 || z == 2) ? 1 : 0);
}

__global__ __launch_bounds__(256) void gemm1_kernel(const float* __restrict__ A, const float* __restrict__ W,
                                                    const float* __restrict__ bias, float* __restrict__ C) {
    gemm_body(A, W, bias, C, 0);
}

// ---------------- FFT over 4096 complex points: 3 register-resident radix-16 super-stages
#define IDX(i) ((i) + ((i) >> 5))
#define A_ELEMS (NFFT + NFFT / 32)                 // 4224 float2
#define TW_ELEMS (NFFT / 2 + NFFT / 64)            // 2112 float2
#define FFT_SMEM ((A_ELEMS + TW_ELEMS) * 8)        // 50688 bytes

__device__ __forceinline__ float2 cmul(float2 a, float2 b) {
    return make_float2(a.x * b.x - a.y * b.y, a.x * b.y + a.y * b.x);
}

// base-4 digit reversal of a 12-bit index
__device__ __forceinline__ int dr4(int i) {
    int r = __brev(i) >> 20;
    return ((r & 0x555) << 1) | ((r >> 1) & 0x555);
}

__device__ __forceinline__ void bfly4(float2& a0, float2& a1, float2& a2, float2& a3,
                                      float2 w1, float2 w2, float2 w3) {
    float2 t1 = cmul(a1, w1);
    float2 t2 = cmul(a2, w2);
    float2 t3 = cmul(a3, w3);
    float u0x = a0.x + t2.x, u0y = a0.y + t2.y;
    float u1x = a0.x - t2.x, u1y = a0.y - t2.y;
    float u2x = t1.x + t3.x, u2y = t1.y + t3.y;
    float u3x = t1.x - t3.x, u3y = t1.y - t3.y;
    a0 = make_float2(u0x + u2x, u0y + u2y);
    a1 = make_float2(u1x + u3y, u1y - u3x);   // u1 - i*u3
    a2 = make_float2(u0x - u2x, u0y - u2y);
    a3 = make_float2(u1x - u3y, u1y + u3x);   // u1 + i*u3
}

__device__ __forceinline__ void fft4096_r16(float2* A, const float2* TW) {
    int g = threadIdx.x;   // 256 groups of 16 points
#pragma unroll
    for (int t = 0; t < 3; t++) {
        __syncthreads();
        const int fourt = 4 * t;
        const int L = 1 << fourt;
        const int p = g & (L - 1);
        const int base = ((g >> fourt) << (fourt + 4)) + p;
        const int sh = 10 - fourt;
        float2 x[16];
#pragma unroll
        for (int q = 0; q < 16; q++) x[q] = A[IDX(base + (q << fourt))];
        {
            float2 w1 = TW[IDX(p << sh)];
            float2 w2 = TW[IDX((p << sh) << 1)];
            float2 w3 = cmul(w1, w2);
#pragma unroll
            for (int r = 0; r < 4; r++)
                bfly4(x[4 * r], x[4 * r + 1], x[4 * r + 2], x[4 * r + 3], w1, w2, w3);
        }
#pragma unroll
        for (int q0 = 0; q0 < 4; q0++) {
            int idx = (p + (q0 << fourt)) << (sh - 2);
            float2 w1 = TW[IDX(idx)];
            float2 w2 = TW[IDX(idx << 1)];
            float2 w3 = cmul(w1, w2);
            bfly4(x[q0], x[q0 + 4], x[q0 + 8], x[q0 + 12], w1, w2, w3);
        }
#pragma unroll
        for (int q = 0; q < 16; q++) A[IDX(base + (q << fourt))] = x[q];
    }
    __syncthreads();
}

__device__ __forceinline__ void make_tw(float2* TW) {
    for (int t = threadIdx.x; t < NFFT / 2; t += 256) {
        float s, co;
        __sincosf(-6.283185307179586f * (float)t / (float)NFFT, &s, &co);
        TW[IDX(t)] = make_float2(co, s);
    }
}

// Precompute filter spectra: one complex FFT per CHANNEL PAIR (f_{2p} + i f_{2p+1}).
__global__ __launch_bounds__(256) void filtfft_kernel() {
    extern __shared__ float2 smf[];
    float2* F  = smf;                 // swizzled, 4224
    float2* TW = smf + A_ELEMS;       // swizzled, 2112
    int pb = blockIdx.x, tid = threadIdx.x;  // 256 threads, 256 blocks
    int c0 = 2 * pb;
    make_tw(TW);
    __syncthreads();
    for (int i = tid; i < NFFT; i += 256) {
        int r = dr4(i);
        float v0 = 0.f, v1 = 0.f;
        if (r < LSEQ) { v0 = g_filt[r * DMODEL + c0]; v1 = g_filt[r * DMODEL + c0 + 1]; }
        F[IDX(i)] = make_float2(v0, v1);
    }
    fft4096_r16(F, TW);
    float2* Gp = g_Ff + (size_t)pb * NFFT;
    for (int t = tid; t < NFFT; t += 256) Gp[t] = F[IDX(t)];
}

// Causal conv via FFT: z = k_norm + i*v_norm per channel; filter spectrum
// reconstructed on the fly from the packed pair spectrum (conjugate symmetry).
__global__ __launch_bounds__(256) void fftconv_kernel() {
    extern __shared__ float2 smf[];
    float2* Z  = smf;                 // swizzled, 4224
    float2* TW = smf + A_ELEMS;       // swizzled, 2112
    int c = blockIdx.x, tid = threadIdx.x;  // 256 threads, 512 blocks
    make_tw(TW);
    __syncthreads();
    for (int i = tid; i < NFFT; i += 256) {
        int r = dr4(i);
        float kr = 0.f, vi = 0.f;
        if (r < LSEQ) { kr = g_k[r * DMODEL + c]; vi = g_v[r * DMODEL + c]; }
        Z[IDX(i)] = make_float2(kr, vi);
    }
    fft4096_r16(Z, TW);
    const float2* Gp = g_Ff + (size_t)(c >> 1) * NFFT;
    int par = c & 1;
    float2 y[16];
#pragma unroll
    for (int jj = 0; jj < 16; jj++) {
        int t = tid + jj * 256;
        float2 Gt = Gp[t];
        float2 Gr = Gp[(NFFT - t) & (NFFT - 1)];
        float Ax = 0.5f * (Gt.x + Gr.x), Ay = 0.5f * (Gt.y - Gr.y);
        float Dx = 0.5f * (Gt.x - Gr.x), Dy = 0.5f * (Gt.y + Gr.y);
        float Fx = par ? Dy : Ax;
        float Fy = par ? -Dx : Ay;
        float2 z = Z[IDX(t)];
        float pr = z.x * Fx - z.y * Fy;
        float pi = z.x * Fy + z.y * Fx;
        y[jj] = make_float2(pr, -pi);   // conj for IFFT-via-FFT
    }
    __syncthreads();
#pragma unroll
    for (int jj = 0; jj < 16; jj++) {
        int i = tid + jj * 256;
        Z[IDX(dr4(i))] = y[jj];
    }
    fft4096_r16(Z, TW);
    const float invN = 1.f / (float)NFFT;
    for (int t = tid; t < LSEQ; t += 256) {
        float2 w = Z[IDX(t)];
        g_kf[t * DMODEL + c] =  w.x * invN;   // Re(conj) = Re
        g_vf[t * DMODEL + c] = -w.y * invN;   // Im(conj) = -Im
    }
}

// ---------------- fused gates + chunk rank-1 sums, per (head, chunk) ----------------
// Two register-tiled 64x64x64 mini-GEMMs per block:
//   U = V . Wsc,  g_i = relu(<U_i, K_i> + b)^2 + eps,  S = (g (.) V)^T . K
#define TP 65   // padded row stride (kills bank conflicts on column access)
__global__ __launch_bounds__(256) void gatechunk_kernel(const float* __restrict__ wgz_w,
                                                        const float* __restrict__ wgz_b,
                                                        const float* __restrict__ scale) {
    extern __shared__ float sm[];
    float* ks  = sm;                  // 64*65
    float* vs  = sm + TCH * TP;       // 64*65
    float* Wu  = sm + 2 * TCH * TP;   // Wsc [d*64+e], later reused as U [i*65+e]
    float* gs  = sm + 2 * TCH * TP + HD * TP;  // 64
    int hb = blockIdx.x;              // 256 blocks: h*32 + c
    int h = hb >> 5, c = hb & 31;
    int tid = threadIdx.x;            // 256
    int l0 = c * TCH;
    for (int idx = tid; idx < TCH * HD; idx += 256) {
        int row = idx >> 6, col = idx & 63;
        int ga = (l0 + row) * DMODEL + h * HD + col;
        ks[row * TP + col] = g_kf[ga];
        vs[row * TP + col] = g_vf[ga];
    }
    for (int idx = tid; idx < HD * HD; idx += 256) Wu[idx] = wgz_w[idx] * scale[idx];
    __syncthreads();

    // U = V . Wsc  (thread -> 4x4 block of U)
    int rg = tid >> 4, cg = tid & 15;     // 16 row groups x 16 col groups
    float au[4][4];
#pragma unroll
    for (int i = 0; i < 4; i++)
#pragma unroll
        for (int j = 0; j < 4; j++) au[i][j] = 0.f;
    for (int d = 0; d < HD; d++) {
        float a[4], b[4];
#pragma unroll
        for (int r = 0; r < 4; r++) a[r] = vs[(rg * 4 + r) * TP + d];
#pragma unroll
        for (int cc = 0; cc < 4; cc++) b[cc] = Wu[d * 64 + cg * 4 + cc];
#pragma unroll
        for (int r = 0; r < 4; r++)
#pragma unroll
            for (int cc = 0; cc < 4; cc++) au[r][cc] += a[r] * b[cc];
    }
    __syncthreads();   // all Wsc reads done; reuse Wu as U
#pragma unroll
    for (int r = 0; r < 4; r++)
#pragma unroll
        for (int cc = 0; cc < 4; cc++) Wu[(rg * 4 + r) * TP + cg * 4 + cc] = au[r][cc];
    __syncthreads();

    // gates: warp w -> positions w*8 .. w*8+7
    {
        int w = tid >> 5, lane = tid & 31;
        float bias0 = wgz_b[0];
#pragma unroll
        for (int ii = 0; ii < 8; ii++) {
            int i = w * 8 + ii;
            float acc = Wu[i * TP + lane] * ks[i * TP + lane]
                      + Wu[i * TP + lane + 32] * ks[i * TP + lane + 32];
#pragma unroll
            for (int o = 16; o; o >>= 1) acc += __shfl_xor_sync(0xffffffffu, acc, o);
            if (lane == 0) {
                float r = fmaxf(acc + bias0, 0.f);
                float gv = r * r + EPSF;
                gs[i] = gv;
                g_gate[h * LSEQ + l0 + i] = gv;
            }
        }
    }
    __syncthreads();

    // S[d,e] = sum_i gs[i] * vs[i,d] * ks[i,e]   (thread -> 4x4 block of S)
    float as[4][4];
#pragma unroll
    for (int i = 0; i < 4; i++)
#pragma unroll
        for (int j = 0; j < 4; j++) as[i][j] = 0.f;
    for (int i = 0; i < TCH; i++) {
        float gg = gs[i];
        float a[4], b[4];
#pragma unroll
        for (int r = 0; r < 4; r++) a[r] = gg * vs[i * TP + rg * 4 + r];
#pragma unroll
        for (int cc = 0; cc < 4; cc++) b[cc] = ks[i * TP + cg * 4 + cc];
#pragma unroll
        for (int r = 0; r < 4; r++)
#pragma unroll
            for (int cc = 0; cc < 4; cc++) as[r][cc] += a[r] * b[cc];
    }
    float* Sp = g_S + (size_t)hb * HD * HD;
#pragma unroll
    for (int r = 0; r < 4; r++)
#pragma unroll
        for (int cc = 0; cc < 4; cc++) Sp[(rg * 4 + r) * 64 + cg * 4 + cc] = as[r][cc];
}
#define GC_SMEM ((2 * TCH * TP + HD * TP + TCH) * 4)

// ---------------- exclusive prefix over chunks (state matrices + gate sums) ----------------
__global__ void prefix_kernel() {
    int h = blockIdx.x, tid = threadIdx.x;  // 512
    __shared__ float gc[NCHUNK];
    if (tid < NCHUNK) {
        float s = 0.f;
        for (int i = 0; i < TCH; i++) s += g_gate[h * LSEQ + tid * TCH + i];
        gc[tid] = s;
    }
    __syncthreads();
    if (tid == 0) {
        float run = 0.f;
        for (int c = 0; c < NCHUNK; c++) { float t = gc[c]; g_Gpre[h * NCHUNK + c] = run; run += t; }
    }
    for (int idx = tid; idx < HD * HD; idx += 512) {
        float run = 0.f;
#pragma unroll
        for (int c = 0; c < NCHUNK; c++) {
            size_t off = ((size_t)(h * NCHUNK + c)) * HD * HD + idx;
            float t = g_S[off];
            g_Spre[off] = run;
            run += t;
        }
    }
}

// ---------------- intra-chunk scan + readout (256 threads: 4 threads per column e) -------
__global__ __launch_bounds__(256) void scan_readout_kernel(const float* __restrict__ scale) {
    extern __shared__ float sm[];
    float* qs = sm;                     // 64*64
    float* ks = sm + TCH * HD;
    float* vs = sm + 2 * TCH * HD;
    float* gs = sm + 3 * TCH * HD;      // 64
    int hb = blockIdx.x;                // 256 blocks: h*32 + c
    int h = hb >> 5, c = hb & 31;
    int tid = threadIdx.x;              // 256
    int l0 = c * TCH;
    for (int idx = tid; idx < TCH * HD; idx += 256) {
        int row = idx >> 6, col = idx & 63;
        int ga = (l0 + row) * DMODEL + h * HD + col;
        qs[idx] = g_q[ga];
        ks[idx] = g_kf[ga];
        vs[idx] = g_vf[ga];
    }
    if (tid < TCH) gs[tid] = g_gate[h * LSEQ + l0 + tid];
    int e = tid >> 2, quarter = tid & 3, d0 = quarter * 16;
    float M[16], sc[16];
    {
        const float* Sp = g_Spre + (size_t)hb * HD * HD;
#pragma unroll
        for (int j = 0; j < 16; j++) {
            M[j]  = Sp[(d0 + j) * 64 + e];
            sc[j] = scale[(d0 + j) * 64 + e];
        }
    }
    float G = g_Gpre[h * NCHUNK + c];
    __syncthreads();
    const float4* q4 = reinterpret_cast<const float4*>(qs);
    const float4* v4 = reinterpret_cast<const float4*>(vs);
    int o4 = quarter * 4;
    for (int i = 0; i < TCH; i++) {
        float gg = gs[i]; G += gg;
        float ke = ks[i * HD + e];
        float gk = gg * ke;
        float r = 0.f;
#pragma unroll
        for (int j4 = 0; j4 < 4; j4++) {
            float4 vv = v4[i * 16 + o4 + j4];
            float4 qq = q4[i * 16 + o4 + j4];
            int jb = j4 * 4;
            M[jb + 0] += gk * vv.x; r += qq.x * (sc[jb + 0] * M[jb + 0]);
            M[jb + 1] += gk * vv.y; r += qq.y * (sc[jb + 1] * M[jb + 1]);
            M[jb + 2] += gk * vv.z; r += qq.z * (sc[jb + 2] * M[jb + 2]);
            M[jb + 3] += gk * vv.w; r += qq.w * (sc[jb + 3] * M[jb + 3]);
        }
        r += __shfl_xor_sync(0xffffffffu, r, 1);
        r += __shfl_xor_sync(0xffffffffu, r, 2);
        if (quarter == 0) g_sraw[(l0 + i) * DMODEL + h * HD + e] = r / fmaxf(G, EPSF);
    }
}
#define SR_SMEM ((3 * TCH * HD + TCH) * 4)

// ---------------- l2-normalize sp per (l, head), in place ----------------
__global__ void spnorm_kernel() {
    int tid = threadIdx.x;          // 256
    int w = tid >> 5, lane = tid & 31;
    int p = blockIdx.x * 8 + w;     // l*8 + h
    int l = p >> 3, h = p & 7;
    float* base = g_sraw + l * DMODEL + h * HD;
    float a = base[lane], b = base[lane + 32];
    float ss = a * a + b * b;
#pragma unroll
    for (int o = 16; o; o >>= 1) ss += __shfl_xor_sync(0xffffffffu, ss, o);
    float inv = 1.f / fmaxf(sqrtf(ss), EPSF);
    base[lane] = a * inv;
    base[lane + 32] = b * inv;
}

// ---------------- launch ----------------
extern "C" void kernel_launch(void* const* d_in, const int* in_sizes, int n_in,
                              void* d_out, int out_size) {
    const float* x     = (const float*)d_in[0];
    const float* sb    = (const float*)d_in[1];
    const float* wq_w  = (const float*)d_in[2];
    const float* wq_b  = (const float*)d_in[3];
    const float* wk_w  = (const float*)d_in[4];
    const float* wk_b  = (const float*)d_in[5];
    const float* wv_w  = (const float*)d_in[6];
    const float* wv_b  = (const float*)d_in[7];
    const float* wo_w  = (const float*)d_in[8];
    const float* wo_b  = (const float*)d_in[9];
    const float* td_w  = (const float*)d_in[10];
    const float* td_b  = (const float*)d_in[11];
    const float* wgz_w = (const float*)d_in[12];
    const float* wgz_b = (const float*)d_in[13];
    const float* kvs   = (const float*)d_in[14];
    float* out = (float*)d_out;

    float* sp;
    cudaGetSymbolAddress((void**)&sp, g_sraw);

    cudaFuncSetAttribute(filtfft_kernel, cudaFuncAttributeMaxDynamicSharedMemorySize, FFT_SMEM);
    cudaFuncSetAttribute(fftconv_kernel, cudaFuncAttributeMaxDynamicSharedMemorySize, FFT_SMEM);
    cudaFuncSetAttribute(gatechunk_kernel, cudaFuncAttributeMaxDynamicSharedMemorySize, GC_SMEM);
    cudaFuncSetAttribute(scan_readout_kernel, cudaFuncAttributeMaxDynamicSharedMemorySize, SR_SMEM);

    dim3 g4(DMODEL / 64, LSEQ / 64, 4);
    gemm4_kernel<<<g4, 256>>>(x, sb, wq_w, wk_w, wv_w, td_w, wq_b, wk_b, wv_b, td_b);
    filtfft_kernel<<<DMODEL / 2, 256, FFT_SMEM>>>();
    fftconv_kernel<<<DMODEL, 256, FFT_SMEM>>>();
    gatechunk_kernel<<<NH * NCHUNK, 256, GC_SMEM>>>(wgz_w, wgz_b, kvs);
    prefix_kernel<<<NH, 512>>>();
    scan_readout_kernel<<<NH * NCHUNK, 256, SR_SMEM>>>(kvs);
    spnorm_kernel<<<(LSEQ * NH) / 8, 256>>>();
    dim3 g1(DMODEL / 64, LSEQ / 64, 1);
    gemm1_kernel<<<g1, 256>>>(sp, wo_w, wo_b, out);
}

// round 13
// speedup vs baseline: 1.4067x; 1.4067x over previous
#include <cuda_runtime.h>
#include <math.h>

#define LSEQ 2048
#define DMODEL 512
#define NH 8
#define HD 64
#define NFFT 4096
#define EPSF 1e-5f
#define NCHUNK 16
#define TCH 128

typedef unsigned long long u64;

// ---------------- scratch (device globals; no runtime allocation) ----------------
__device__ float g_q[LSEQ * DMODEL];
__device__ float g_k[LSEQ * DMODEL];
__device__ float g_v[LSEQ * DMODEL];
__device__ float g_filt[LSEQ * DMODEL];
__device__ float g_kf[LSEQ * DMODEL];
__device__ float g_vf[LSEQ * DMODEL];
__device__ float g_gate[NH * LSEQ];
__device__ float g_S[NH * NCHUNK * HD * HD];
__device__ float g_Spre[NH * NCHUNK * HD * HD];
__device__ float g_Gpre[NH * NCHUNK];
__device__ float g_sraw[LSEQ * DMODEL];
__device__ float2 g_Ff[(DMODEL / 2) * NFFT];   // packed filter spectra (2 channels/FFT)

// ---------------- packed f32x2 helpers (sm_103a FFMA2 path) ----------------
__device__ __forceinline__ u64 pk2(float v) {
    u64 r; asm("mov.b64 %0, {%1, %1};" : "=l"(r) : "f"(v)); return r;
}
__device__ __forceinline__ void upk2(u64 v, float& lo, float& hi) {
    asm("mov.b64 {%0, %1}, %2;" : "=f"(lo), "=f"(hi) : "l"(v));
}
__device__ __forceinline__ u64 ffma2(u64 a, u64 b, u64 c) {
    u64 d; asm("fma.rn.f32x2 %0, %1, %2, %3;" : "=l"(d) : "l"(a), "l"(b), "l"(c)); return d;
}

// ---------------- double-buffered GEMM body: C[m,n] = sum_k A[m,k]*W[n,k] + bias[n] -------
// 64x64 tile, 256 threads, 4x4 acc (packed f32x2), K=N=512 fixed.
// l2n != 0: L2-normalize each 64-wide output row segment (N-tile == one head).
__device__ __forceinline__ void gemm_body(const float* __restrict__ A, const float* __restrict__ W,
                                          const float* __restrict__ bias, float* __restrict__ C,
                                          int l2n) {
    __shared__ __align__(16) float As[2][16][68];
    __shared__ __align__(16) float Ws[2][16][68];
    int tid = threadIdx.x;                 // 256 threads
    int bm = blockIdx.y * 64, bn = blockIdx.x * 64;
    int row = tid >> 2, kc = (tid & 3) << 2;
    int tx = tid & 15, ty = tid >> 4;
    const float* Ap = A + (size_t)(bm + row) * DMODEL + kc;
    const float* Wp = W + (size_t)(bn + row) * DMODEL + kc;

    u64 acc2[4][2];
#pragma unroll
    for (int i = 0; i < 4; i++) { acc2[i][0] = 0ull; acc2[i][1] = 0ull; }

    // preload tile 0
    {
        float4 a4 = *reinterpret_cast<const float4*>(Ap);
        float4 w4 = *reinterpret_cast<const float4*>(Wp);
        As[0][kc + 0][row] = a4.x; As[0][kc + 1][row] = a4.y; As[0][kc + 2][row] = a4.z; As[0][kc + 3][row] = a4.w;
        Ws[0][kc + 0][row] = w4.x; Ws[0][kc + 1][row] = w4.y; Ws[0][kc + 2][row] = w4.z; Ws[0][kc + 3][row] = w4.w;
    }
    __syncthreads();

    int buf = 0;
    for (int k0 = 16; k0 <= DMODEL; k0 += 16) {
        float4 a4n, w4n;
        bool more = (k0 < DMODEL);
        if (more) {
            a4n = *reinterpret_cast<const float4*>(Ap + k0);
            w4n = *reinterpret_cast<const float4*>(Wp + k0);
        }
#pragma unroll
        for (int kk = 0; kk < 16; kk++) {
            const u64* bp = reinterpret_cast<const u64*>(&Ws[buf][kk][tx * 4]);
            u64 b0 = bp[0], b1 = bp[1];
#pragma unroll
            for (int i = 0; i < 4; i++) {
                u64 ap = pk2(As[buf][kk][ty * 4 + i]);
                acc2[i][0] = ffma2(ap, b0, acc2[i][0]);
                acc2[i][1] = ffma2(ap, b1, acc2[i][1]);
            }
        }
        if (more) {
            int nb = buf ^ 1;
            As[nb][kc + 0][row] = a4n.x; As[nb][kc + 1][row] = a4n.y; As[nb][kc + 2][row] = a4n.z; As[nb][kc + 3][row] = a4n.w;
            Ws[nb][kc + 0][row] = w4n.x; Ws[nb][kc + 1][row] = w4n.y; Ws[nb][kc + 2][row] = w4n.z; Ws[nb][kc + 3][row] = w4n.w;
            __syncthreads();
        }
        buf ^= 1;
    }
    float4 bb = *reinterpret_cast<const float4*>(bias + bn + tx * 4);
#pragma unroll
    for (int i = 0; i < 4; i++) {
        float c0, c1, c2, c3;
        upk2(acc2[i][0], c0, c1);
        upk2(acc2[i][1], c2, c3);
        c0 += bb.x; c1 += bb.y; c2 += bb.z; c3 += bb.w;
        if (l2n) {
            float ss = c0 * c0 + c1 * c1 + c2 * c2 + c3 * c3;
            ss += __shfl_xor_sync(0xffffffffu, ss, 1);
            ss += __shfl_xor_sync(0xffffffffu, ss, 2);
            ss += __shfl_xor_sync(0xffffffffu, ss, 4);
            ss += __shfl_xor_sync(0xffffffffu, ss, 8);
            float inv = 1.f / fmaxf(sqrtf(ss), EPSF);
            c0 *= inv; c1 *= inv; c2 *= inv; c3 *= inv;
        }
        *reinterpret_cast<float4*>(C + (size_t)(bm + ty * 4 + i) * DMODEL + bn + tx * 4)
            = make_float4(c0, c1, c2, c3);
    }
}

// fused Q/K/V/filter projections: blockIdx.z selects the GEMM (1024 blocks total)
__global__ __launch_bounds__(256) void gemm4_kernel(
    const float* __restrict__ x, const float* __restrict__ sb,
    const float* __restrict__ Wq, const float* __restrict__ Wk,
    const float* __restrict__ Wv, const float* __restrict__ Wt,
    const float* __restrict__ bq, const float* __restrict__ bk,
    const float* __restrict__ bv, const float* __restrict__ bt) {
    int z = blockIdx.z;
    const float* A = (z == 3) ? sb : x;
    const float* W = (z == 0) ? Wq : (z == 1) ? Wk : (z == 2) ? Wv : Wt;
    const float* b = (z == 0) ? bq : (z == 1) ? bk : (z == 2) ? bv : bt;
    float* C = (z == 0) ? g_q : (z == 1) ? g_k : (z == 2) ? g_v : g_filt;
    gemm_body(A, W, b, C, (z == 1 || z == 2) ? 1 : 0);
}

__global__ __launch_bounds__(256) void gemm1_kernel(const float* __restrict__ A, const float* __restrict__ W,
                                                    const float* __restrict__ bias, float* __restrict__ C) {
    gemm_body(A, W, bias, C, 0);
}

// ---------------- FFT over 4096 complex points: 3 register-resident radix-16 super-stages
#define IDX(i) ((i) + ((i) >> 5))
#define A_ELEMS (NFFT + NFFT / 32)                 // 4224 float2
#define TW_ELEMS (NFFT / 2 + NFFT / 64)            // 2112 float2
#define FFT_SMEM ((A_ELEMS + TW_ELEMS) * 8)        // 50688 bytes

__device__ __forceinline__ float2 cmul(float2 a, float2 b) {
    return make_float2(a.x * b.x - a.y * b.y, a.x * b.y + a.y * b.x);
}

// base-4 digit reversal of a 12-bit index
__device__ __forceinline__ int dr4(int i) {
    int r = __brev(i) >> 20;
    return ((r & 0x555) << 1) | ((r >> 1) & 0x555);
}

__device__ __forceinline__ void bfly4(float2& a0, float2& a1, float2& a2, float2& a3,
                                      float2 w1, float2 w2, float2 w3) {
    float2 t1 = cmul(a1, w1);
    float2 t2 = cmul(a2, w2);
    float2 t3 = cmul(a3, w3);
    float u0x = a0.x + t2.x, u0y = a0.y + t2.y;
    float u1x = a0.x - t2.x, u1y = a0.y - t2.y;
    float u2x = t1.x + t3.x, u2y = t1.y + t3.y;
    float u3x = t1.x - t3.x, u3y = t1.y - t3.y;
    a0 = make_float2(u0x + u2x, u0y + u2y);
    a1 = make_float2(u1x + u3y, u1y - u3x);   // u1 - i*u3
    a2 = make_float2(u0x - u2x, u0y - u2y);
    a3 = make_float2(u1x - u3y, u1y + u3x);   // u1 + i*u3
}

__device__ __forceinline__ void fft4096_r16(float2* A, const float2* TW) {
    int g = threadIdx.x;   // 256 groups of 16 points
#pragma unroll
    for (int t = 0; t < 3; t++) {
        __syncthreads();
        const int fourt = 4 * t;
        const int L = 1 << fourt;
        const int p = g & (L - 1);
        const int base = ((g >> fourt) << (fourt + 4)) + p;
        const int sh = 10 - fourt;
        float2 x[16];
#pragma unroll
        for (int q = 0; q < 16; q++) x[q] = A[IDX(base + (q << fourt))];
        {
            float2 w1 = TW[IDX(p << sh)];
            float2 w2 = TW[IDX((p << sh) << 1)];
            float2 w3 = cmul(w1, w2);
#pragma unroll
            for (int r = 0; r < 4; r++)
                bfly4(x[4 * r], x[4 * r + 1], x[4 * r + 2], x[4 * r + 3], w1, w2, w3);
        }
#pragma unroll
        for (int q0 = 0; q0 < 4; q0++) {
            int idx = (p + (q0 << fourt)) << (sh - 2);
            float2 w1 = TW[IDX(idx)];
            float2 w2 = TW[IDX(idx << 1)];
            float2 w3 = cmul(w1, w2);
            bfly4(x[q0], x[q0 + 4], x[q0 + 8], x[q0 + 12], w1, w2, w3);
        }
#pragma unroll
        for (int q = 0; q < 16; q++) A[IDX(base + (q << fourt))] = x[q];
    }
    __syncthreads();
}

__device__ __forceinline__ void make_tw(float2* TW) {
    for (int t = threadIdx.x; t < NFFT / 2; t += 256) {
        float s, co;
        __sincosf(-6.283185307179586f * (float)t / (float)NFFT, &s, &co);
        TW[IDX(t)] = make_float2(co, s);
    }
}

// Precompute filter spectra: one complex FFT per CHANNEL PAIR (f_{2p} + i f_{2p+1}).
__global__ __launch_bounds__(256) void filtfft_kernel() {
    extern __shared__ float2 smf[];
    float2* F  = smf;                 // swizzled, 4224
    float2* TW = smf + A_ELEMS;       // swizzled, 2112
    int pb = blockIdx.x, tid = threadIdx.x;  // 256 threads, 256 blocks
    int c0 = 2 * pb;
    make_tw(TW);
    __syncthreads();
    for (int i = tid; i < NFFT; i += 256) {
        int r = dr4(i);
        float v0 = 0.f, v1 = 0.f;
        if (r < LSEQ) { v0 = g_filt[r * DMODEL + c0]; v1 = g_filt[r * DMODEL + c0 + 1]; }
        F[IDX(i)] = make_float2(v0, v1);
    }
    fft4096_r16(F, TW);
    float2* Gp = g_Ff + (size_t)pb * NFFT;
    for (int t = tid; t < NFFT; t += 256) Gp[t] = F[IDX(t)];
}

// Causal conv via FFT: z = k_norm + i*v_norm per channel; filter spectrum
// reconstructed on the fly from the packed pair spectrum (conjugate symmetry).
__global__ __launch_bounds__(256) void fftconv_kernel() {
    extern __shared__ float2 smf[];
    float2* Z  = smf;                 // swizzled, 4224
    float2* TW = smf + A_ELEMS;       // swizzled, 2112
    int c = blockIdx.x, tid = threadIdx.x;  // 256 threads, 512 blocks
    make_tw(TW);
    __syncthreads();
    for (int i = tid; i < NFFT; i += 256) {
        int r = dr4(i);
        float kr = 0.f, vi = 0.f;
        if (r < LSEQ) { kr = g_k[r * DMODEL + c]; vi = g_v[r * DMODEL + c]; }
        Z[IDX(i)] = make_float2(kr, vi);
    }
    fft4096_r16(Z, TW);
    const float2* Gp = g_Ff + (size_t)(c >> 1) * NFFT;
    int par = c & 1;
    float2 y[16];
#pragma unroll
    for (int jj = 0; jj < 16; jj++) {
        int t = tid + jj * 256;
        float2 Gt = Gp[t];
        float2 Gr = Gp[(NFFT - t) & (NFFT - 1)];
        float Ax = 0.5f * (Gt.x + Gr.x), Ay = 0.5f * (Gt.y - Gr.y);
        float Dx = 0.5f * (Gt.x - Gr.x), Dy = 0.5f * (Gt.y + Gr.y);
        float Fx = par ? Dy : Ax;
        float Fy = par ? -Dx : Ay;
        float2 z = Z[IDX(t)];
        float pr = z.x * Fx - z.y * Fy;
        float pi = z.x * Fy + z.y * Fx;
        y[jj] = make_float2(pr, -pi);   // conj for IFFT-via-FFT
    }
    __syncthreads();
#pragma unroll
    for (int jj = 0; jj < 16; jj++) {
        int i = tid + jj * 256;
        Z[IDX(dr4(i))] = y[jj];
    }
    fft4096_r16(Z, TW);
    const float invN = 1.f / (float)NFFT;
    for (int t = tid; t < LSEQ; t += 256) {
        float2 w = Z[IDX(t)];
        g_kf[t * DMODEL + c] =  w.x * invN;   // Re(conj) = Re
        g_vf[t * DMODEL + c] = -w.y * invN;   // Im(conj) = -Im
    }
}

// ---------------- gates: g_l = relu(v_f^T (W .* scale) k_f + b)^2 + eps ----------------
// Each warp processes 4 consecutive positions, reusing every Wsc shared load x4.
__global__ __launch_bounds__(256) void gates_kernel(const float* __restrict__ wgz_w,
                                                    const float* __restrict__ wgz_b,
                                                    const float* __restrict__ scale) {
    __shared__ float Wsc[HD * HD];
    int tid = threadIdx.x;  // 256
    for (int i = tid; i < HD * HD; i += 256) Wsc[i] = wgz_w[i] * scale[i];
    __syncthreads();
    int w = tid >> 5, lane = tid & 31;
    int pb = blockIdx.x * 32 + w * 4;     // p = h*2048 + l; 4 consecutive l, same h
    int h = pb >> 11, l = pb & (LSEQ - 1);
    const float* vr0 = g_vf + (l + 0) * DMODEL + h * HD;
    const float* vr1 = g_vf + (l + 1) * DMODEL + h * HD;
    const float* vr2 = g_vf + (l + 2) * DMODEL + h * HD;
    const float* vr3 = g_vf + (l + 3) * DMODEL + h * HD;
    float aA0 = 0.f, aA1 = 0.f, aA2 = 0.f, aA3 = 0.f;
    float aB0 = 0.f, aB1 = 0.f, aB2 = 0.f, aB3 = 0.f;
#pragma unroll 8
    for (int d = 0; d < HD; d++) {
        float w0 = Wsc[d * 64 + lane];
        float w1 = Wsc[d * 64 + lane + 32];
        float v0 = vr0[d], v1 = vr1[d], v2 = vr2[d], v3 = vr3[d];
        aA0 += v0 * w0; aB0 += v0 * w1;
        aA1 += v1 * w0; aB1 += v1 * w1;
        aA2 += v2 * w0; aB2 += v2 * w1;
        aA3 += v3 * w0; aB3 += v3 * w1;
    }
    float bias0 = wgz_b[0];
    const float* kr0 = g_kf + (l + 0) * DMODEL + h * HD;
    const float* kr1 = g_kf + (l + 1) * DMODEL + h * HD;
    const float* kr2 = g_kf + (l + 2) * DMODEL + h * HD;
    const float* kr3 = g_kf + (l + 3) * DMODEL + h * HD;
    float p0 = aA0 * kr0[lane] + aB0 * kr0[lane + 32];
    float p1 = aA1 * kr1[lane] + aB1 * kr1[lane + 32];
    float p2 = aA2 * kr2[lane] + aB2 * kr2[lane + 32];
    float p3 = aA3 * kr3[lane] + aB3 * kr3[lane + 32];
#pragma unroll
    for (int o = 16; o; o >>= 1) {
        p0 += __shfl_xor_sync(0xffffffffu, p0, o);
        p1 += __shfl_xor_sync(0xffffffffu, p1, o);
        p2 += __shfl_xor_sync(0xffffffffu, p2, o);
        p3 += __shfl_xor_sync(0xffffffffu, p3, o);
    }
    if (lane < 4) {
        float pj = (lane == 0) ? p0 : (lane == 1) ? p1 : (lane == 2) ? p2 : p3;
        float r = fmaxf(pj + bias0, 0.f);
        g_gate[pb + lane] = r * r + EPSF;
    }
}

// ---------------- per-chunk rank-1 sums: S_c[d,e] = sum_{l in chunk} g_l v_f[l,d] k_f[l,e] ----
__global__ void chunksum_kernel() {
    int hb = blockIdx.x;                  // h*16 + c
    int h = hb >> 4, c = hb & 15;
    int tid = threadIdx.x;                // 128
    int e = tid >> 1, half = tid & 1, d0 = half * 32;
    float acc[32];
#pragma unroll
    for (int j = 0; j < 32; j++) acc[j] = 0.f;
    int l0 = c * TCH;
    for (int i = 0; i < TCH; i++) {
        int l = l0 + i;
        float gg = g_gate[h * LSEQ + l];
        float ke = g_kf[l * DMODEL + h * HD + e];
        float gk = gg * ke;
        const float4* vp = reinterpret_cast<const float4*>(g_vf + l * DMODEL + h * HD + d0);
#pragma unroll
        for (int j4 = 0; j4 < 8; j4++) {
            float4 v4 = vp[j4];
            acc[j4 * 4 + 0] += gk * v4.x;
            acc[j4 * 4 + 1] += gk * v4.y;
            acc[j4 * 4 + 2] += gk * v4.z;
            acc[j4 * 4 + 3] += gk * v4.w;
        }
    }
    float* Sp = g_S + (size_t)hb * HD * HD;
#pragma unroll
    for (int j = 0; j < 32; j++) Sp[(d0 + j) * 64 + e] = acc[j];
}

// ---------------- exclusive prefix over chunks (state matrices + gate sums) ----------------
__global__ void prefix_kernel() {
    int h = blockIdx.x, tid = threadIdx.x;  // 512
    __shared__ float gc[NCHUNK];
    if (tid < NCHUNK) {
        float s = 0.f;
        for (int i = 0; i < TCH; i++) s += g_gate[h * LSEQ + tid * TCH + i];
        gc[tid] = s;
    }
    __syncthreads();
    if (tid == 0) {
        float run = 0.f;
        for (int c = 0; c < NCHUNK; c++) { float t = gc[c]; g_Gpre[h * NCHUNK + c] = run; run += t; }
    }
    for (int idx = tid; idx < HD * HD; idx += 512) {
        float run = 0.f;
#pragma unroll
        for (int c = 0; c < NCHUNK; c++) {
            size_t off = ((size_t)(h * NCHUNK + c)) * HD * HD + idx;
            float t = g_S[off];
            g_Spre[off] = run;
            run += t;
        }
    }
}

// ---------------- intra-chunk scan + readout + fused L2 norm ----------------
// 256 threads: 4 threads per column e. Results staged in smem, normalized in epilogue.
__global__ __launch_bounds__(256) void scan_readout_kernel(const float* __restrict__ scale) {
    extern __shared__ float sm[];
    float* qs = sm;                      // 128*64
    float* ks = sm + TCH * HD;
    float* vs = sm + 2 * TCH * HD;
    float* os = sm + 3 * TCH * HD;       // 128*64 output staging
    float* gs = sm + 4 * TCH * HD;       // 128
    int hb = blockIdx.x;
    int h = hb >> 4, c = hb & 15;
    int tid = threadIdx.x;               // 256
    int l0 = c * TCH;
    for (int idx = tid; idx < TCH * HD; idx += 256) {
        int row = idx >> 6, col = idx & 63;
        int ga = (l0 + row) * DMODEL + h * HD + col;
        qs[idx] = g_q[ga];
        ks[idx] = g_kf[ga];
        vs[idx] = g_vf[ga];
    }
    if (tid < TCH) gs[tid] = g_gate[h * LSEQ + l0 + tid];
    int e = tid >> 2, quarter = tid & 3, d0 = quarter * 16;
    float M[16], sc[16];
    {
        const float* Sp = g_Spre + (size_t)hb * HD * HD;
#pragma unroll
        for (int j = 0; j < 16; j++) {
            M[j]  = Sp[(d0 + j) * 64 + e];
            sc[j] = scale[(d0 + j) * 64 + e];
        }
    }
    float G = g_Gpre[h * NCHUNK + c];
    __syncthreads();
    const float4* q4 = reinterpret_cast<const float4*>(qs);
    const float4* v4 = reinterpret_cast<const float4*>(vs);
    int o4 = quarter * 4;
    for (int i = 0; i < TCH; i++) {
        float gg = gs[i]; G += gg;
        float ke = ks[i * HD + e];
        float gk = gg * ke;
        float r = 0.f;
#pragma unroll
        for (int j4 = 0; j4 < 4; j4++) {
            float4 vv = v4[i * 16 + o4 + j4];
            float4 qq = q4[i * 16 + o4 + j4];
            int jb = j4 * 4;
            M[jb + 0] += gk * vv.x; r += qq.x * (sc[jb + 0] * M[jb + 0]);
            M[jb + 1] += gk * vv.y; r += qq.y * (sc[jb + 1] * M[jb + 1]);
            M[jb + 2] += gk * vv.z; r += qq.z * (sc[jb + 2] * M[jb + 2]);
            M[jb + 3] += gk * vv.w; r += qq.w * (sc[jb + 3] * M[jb + 3]);
        }
        r += __shfl_xor_sync(0xffffffffu, r, 1);
        r += __shfl_xor_sync(0xffffffffu, r, 2);
        if (quarter == 0) os[i * HD + e] = r / fmaxf(G, EPSF);
    }
    __syncthreads();
    // epilogue: per-position L2 norm (identical math to the old spnorm kernel)
    {
        int w = tid >> 5, lane = tid & 31;
        for (int i = w; i < TCH; i += 8) {
            float a = os[i * HD + lane], b = os[i * HD + lane + 32];
            float ss = a * a + b * b;
#pragma unroll
            for (int o = 16; o; o >>= 1) ss += __shfl_xor_sync(0xffffffffu, ss, o);
            float inv = 1.f / fmaxf(sqrtf(ss), EPSF);
            float* outp = g_sraw + (size_t)(l0 + i) * DMODEL + h * HD;
            outp[lane] = a * inv;
            outp[lane + 32] = b * inv;
        }
    }
}
#define SR_SMEM ((4 * TCH * HD + TCH) * 4)

// ---------------- launch ----------------
extern "C" void kernel_launch(void* const* d_in, const int* in_sizes, int n_in,
                              void* d_out, int out_size) {
    const float* x     = (const float*)d_in[0];
    const float* sb    = (const float*)d_in[1];
    const float* wq_w  = (const float*)d_in[2];
    const float* wq_b  = (const float*)d_in[3];
    const float* wk_w  = (const float*)d_in[4];
    const float* wk_b  = (const float*)d_in[5];
    const float* wv_w  = (const float*)d_in[6];
    const float* wv_b  = (const float*)d_in[7];
    const float* wo_w  = (const float*)d_in[8];
    const float* wo_b  = (const float*)d_in[9];
    const float* td_w  = (const float*)d_in[10];
    const float* td_b  = (const float*)d_in[11];
    const float* wgz_w = (const float*)d_in[12];
    const float* wgz_b = (const float*)d_in[13];
    const float* kvs   = (const float*)d_in[14];
    float* out = (float*)d_out;

    float* sp;
    cudaGetSymbolAddress((void**)&sp, g_sraw);

    cudaFuncSetAttribute(filtfft_kernel, cudaFuncAttributeMaxDynamicSharedMemorySize, FFT_SMEM);
    cudaFuncSetAttribute(fftconv_kernel, cudaFuncAttributeMaxDynamicSharedMemorySize, FFT_SMEM);
    cudaFuncSetAttribute(scan_readout_kernel, cudaFuncAttributeMaxDynamicSharedMemorySize, SR_SMEM);

    dim3 g4(DMODEL / 64, LSEQ / 64, 4);
    gemm4_kernel<<<g4, 256>>>(x, sb, wq_w, wk_w, wv_w, td_w, wq_b, wk_b, wv_b, td_b);
    filtfft_kernel<<<DMODEL / 2, 256, FFT_SMEM>>>();
    fftconv_kernel<<<DMODEL, 256, FFT_SMEM>>>();
    gates_kernel<<<(NH * LSEQ) / 32, 256>>>(wgz_w, wgz_b, kvs);
    chunksum_kernel<<<NH * NCHUNK, 128>>>();
    prefix_kernel<<<NH, 512>>>();
    scan_readout_kernel<<<NH * NCHUNK, 256, SR_SMEM>>>(kvs);
    dim3 g1(DMODEL / 64, LSEQ / 64, 1);
    gemm1_kernel<<<g1, 256>>>(sp, wo_w, wo_b, out);
}

// round 14
// speedup vs baseline: 1.4369x; 1.0215x over previous
#include <cuda_runtime.h>
#include <math.h>

#define LSEQ 2048
#define DMODEL 512
#define NH 8
#define HD 64
#define NFFT 4096
#define EPSF 1e-5f
#define NCHUNK 16
#define TCH 128

typedef unsigned long long u64;

// ---------------- scratch (device globals; no runtime allocation) ----------------
__device__ float g_q[LSEQ * DMODEL];
__device__ float g_k[LSEQ * DMODEL];
__device__ float g_v[LSEQ * DMODEL];
__device__ float g_filt[LSEQ * DMODEL];
__device__ float g_kf[LSEQ * DMODEL];
__device__ float g_vf[LSEQ * DMODEL];
__device__ float g_gate[NH * LSEQ];
__device__ float g_S[NH * NCHUNK * HD * HD];
__device__ float g_Spre[NH * NCHUNK * HD * HD];
__device__ float g_Gpre[NH * NCHUNK];
__device__ float g_sraw[LSEQ * DMODEL];
__device__ float2 g_Ff[(DMODEL / 2) * NFFT];   // packed filter spectra (2 channels/FFT)

// ---------------- packed f32x2 helpers (sm_103a FFMA2 path) ----------------
__device__ __forceinline__ u64 pk2(float v) {
    u64 r; asm("mov.b64 %0, {%1, %1};" : "=l"(r) : "f"(v)); return r;
}
__device__ __forceinline__ void upk2(u64 v, float& lo, float& hi) {
    asm("mov.b64 {%0, %1}, %2;" : "=f"(lo), "=f"(hi) : "l"(v));
}
__device__ __forceinline__ u64 ffma2(u64 a, u64 b, u64 c) {
    u64 d; asm("fma.rn.f32x2 %0, %1, %2, %3;" : "=l"(d) : "l"(a), "l"(b), "l"(c)); return d;
}

// ---------------- double-buffered GEMM body: C[m,n] = sum_k A[m,k]*W[n,k] + bias[n] -------
// 64x64 tile, 256 threads, 4x4 acc (packed f32x2), K=N=512 fixed.
// l2n != 0: L2-normalize each 64-wide output row segment (N-tile == one head).
__device__ __forceinline__ void gemm_body(const float* __restrict__ A, const float* __restrict__ W,
                                          const float* __restrict__ bias, float* __restrict__ C,
                                          int l2n) {
    __shared__ __align__(16) float As[2][16][68];
    __shared__ __align__(16) float Ws[2][16][68];
    int tid = threadIdx.x;                 // 256 threads
    int bm = blockIdx.y * 64, bn = blockIdx.x * 64;
    int row = tid >> 2, kc = (tid & 3) << 2;
    int tx = tid & 15, ty = tid >> 4;
    const float* Ap = A + (size_t)(bm + row) * DMODEL + kc;
    const float* Wp = W + (size_t)(bn + row) * DMODEL + kc;

    u64 acc2[4][2];
#pragma unroll
    for (int i = 0; i < 4; i++) { acc2[i][0] = 0ull; acc2[i][1] = 0ull; }

    // preload tile 0
    {
        float4 a4 = *reinterpret_cast<const float4*>(Ap);
        float4 w4 = *reinterpret_cast<const float4*>(Wp);
        As[0][kc + 0][row] = a4.x; As[0][kc + 1][row] = a4.y; As[0][kc + 2][row] = a4.z; As[0][kc + 3][row] = a4.w;
        Ws[0][kc + 0][row] = w4.x; Ws[0][kc + 1][row] = w4.y; Ws[0][kc + 2][row] = w4.z; Ws[0][kc + 3][row] = w4.w;
    }
    __syncthreads();

    int buf = 0;
    for (int k0 = 16; k0 <= DMODEL; k0 += 16) {
        float4 a4n, w4n;
        bool more = (k0 < DMODEL);
        if (more) {
            a4n = *reinterpret_cast<const float4*>(Ap + k0);
            w4n = *reinterpret_cast<const float4*>(Wp + k0);
        }
#pragma unroll
        for (int kk = 0; kk < 16; kk++) {
            const u64* bp = reinterpret_cast<const u64*>(&Ws[buf][kk][tx * 4]);
            u64 b0 = bp[0], b1 = bp[1];
#pragma unroll
            for (int i = 0; i < 4; i++) {
                u64 ap = pk2(As[buf][kk][ty * 4 + i]);
                acc2[i][0] = ffma2(ap, b0, acc2[i][0]);
                acc2[i][1] = ffma2(ap, b1, acc2[i][1]);
            }
        }
        if (more) {
            int nb = buf ^ 1;
            As[nb][kc + 0][row] = a4n.x; As[nb][kc + 1][row] = a4n.y; As[nb][kc + 2][row] = a4n.z; As[nb][kc + 3][row] = a4n.w;
            Ws[nb][kc + 0][row] = w4n.x; Ws[nb][kc + 1][row] = w4n.y; Ws[nb][kc + 2][row] = w4n.z; Ws[nb][kc + 3][row] = w4n.w;
            __syncthreads();
        }
        buf ^= 1;
    }
    float4 bb = *reinterpret_cast<const float4*>(bias + bn + tx * 4);
#pragma unroll
    for (int i = 0; i < 4; i++) {
        float c0, c1, c2, c3;
        upk2(acc2[i][0], c0, c1);
        upk2(acc2[i][1], c2, c3);
        c0 += bb.x; c1 += bb.y; c2 += bb.z; c3 += bb.w;
        if (l2n) {
            float ss = c0 * c0 + c1 * c1 + c2 * c2 + c3 * c3;
            ss += __shfl_xor_sync(0xffffffffu, ss, 1);
            ss += __shfl_xor_sync(0xffffffffu, ss, 2);
            ss += __shfl_xor_sync(0xffffffffu, ss, 4);
            ss += __shfl_xor_sync(0xffffffffu, ss, 8);
            float inv = 1.f / fmaxf(sqrtf(ss), EPSF);
            c0 *= inv; c1 *= inv; c2 *= inv; c3 *= inv;
        }
        *reinterpret_cast<float4*>(C + (size_t)(bm + ty * 4 + i) * DMODEL + bn + tx * 4)
            = make_float4(c0, c1, c2, c3);
    }
}

// fused Q/K/V/filter projections: blockIdx.z selects the GEMM (1024 blocks total)
__global__ __launch_bounds__(256) void gemm4_kernel(
    const float* __restrict__ x, const float* __restrict__ sb,
    const float* __restrict__ Wq, const float* __restrict__ Wk,
    const float* __restrict__ Wv, const float* __restrict__ Wt,
    const float* __restrict__ bq, const float* __restrict__ bk,
    const float* __restrict__ bv, const float* __restrict__ bt) {
    int z = blockIdx.z;
    const float* A = (z == 3) ? sb : x;
    const float* W = (z == 0) ? Wq : (z == 1) ? Wk : (z == 2) ? Wv : Wt;
    const float* b = (z == 0) ? bq : (z == 1) ? bk : (z == 2) ? bv : bt;
    float* C = (z == 0) ? g_q : (z == 1) ? g_k : (z == 2) ? g_v : g_filt;
    gemm_body(A, W, b, C, (z == 1 || z == 2) ? 1 : 0);
}

__global__ __launch_bounds__(256) void gemm1_kernel(const float* __restrict__ A, const float* __restrict__ W,
                                                    const float* __restrict__ bias, float* __restrict__ C) {
    gemm_body(A, W, bias, C, 0);
}

// ---------------- FFT over 4096 complex points: 3 register-resident radix-16 super-stages
#define IDX(i) ((i) + ((i) >> 5))
#define A_ELEMS (NFFT + NFFT / 32)                 // 4224 float2
#define TW_ELEMS (NFFT / 2 + NFFT / 64)            // 2112 float2
#define FFT_SMEM ((A_ELEMS + TW_ELEMS) * 8)        // 50688 bytes

__device__ __forceinline__ float2 cmul(float2 a, float2 b) {
    return make_float2(a.x * b.x - a.y * b.y, a.x * b.y + a.y * b.x);
}

// base-4 digit reversal of a 12-bit index
__device__ __forceinline__ int dr4(int i) {
    int r = __brev(i) >> 20;
    return ((r & 0x555) << 1) | ((r >> 1) & 0x555);
}

__device__ __forceinline__ void bfly4(float2& a0, float2& a1, float2& a2, float2& a3,
                                      float2 w1, float2 w2, float2 w3) {
    float2 t1 = cmul(a1, w1);
    float2 t2 = cmul(a2, w2);
    float2 t3 = cmul(a3, w3);
    float u0x = a0.x + t2.x, u0y = a0.y + t2.y;
    float u1x = a0.x - t2.x, u1y = a0.y - t2.y;
    float u2x = t1.x + t3.x, u2y = t1.y + t3.y;
    float u3x = t1.x - t3.x, u3y = t1.y - t3.y;
    a0 = make_float2(u0x + u2x, u0y + u2y);
    a1 = make_float2(u1x + u3y, u1y - u3x);   // u1 - i*u3
    a2 = make_float2(u0x - u2x, u0y - u2y);
    a3 = make_float2(u1x - u3y, u1y + u3x);   // u1 + i*u3
}

__device__ __forceinline__ void fft4096_r16(float2* A, const float2* TW) {
    int g = threadIdx.x;   // 256 groups of 16 points
#pragma unroll
    for (int t = 0; t < 3; t++) {
        __syncthreads();
        const int fourt = 4 * t;
        const int L = 1 << fourt;
        const int p = g & (L - 1);
        const int base = ((g >> fourt) << (fourt + 4)) + p;
        const int sh = 10 - fourt;
        float2 x[16];
#pragma unroll
        for (int q = 0; q < 16; q++) x[q] = A[IDX(base + (q << fourt))];
        {
            float2 w1 = TW[IDX(p << sh)];
            float2 w2 = TW[IDX((p << sh) << 1)];
            float2 w3 = cmul(w1, w2);
#pragma unroll
            for (int r = 0; r < 4; r++)
                bfly4(x[4 * r], x[4 * r + 1], x[4 * r + 2], x[4 * r + 3], w1, w2, w3);
        }
#pragma unroll
        for (int q0 = 0; q0 < 4; q0++) {
            int idx = (p + (q0 << fourt)) << (sh - 2);
            float2 w1 = TW[IDX(idx)];
            float2 w2 = TW[IDX(idx << 1)];
            float2 w3 = cmul(w1, w2);
            bfly4(x[q0], x[q0 + 4], x[q0 + 8], x[q0 + 12], w1, w2, w3);
        }
#pragma unroll
        for (int q = 0; q < 16; q++) A[IDX(base + (q << fourt))] = x[q];
    }
    __syncthreads();
}

__device__ __forceinline__ void make_tw(float2* TW) {
    for (int t = threadIdx.x; t < NFFT / 2; t += 256) {
        float s, co;
        __sincosf(-6.283185307179586f * (float)t / (float)NFFT, &s, &co);
        TW[IDX(t)] = make_float2(co, s);
    }
}

// Precompute filter spectra: one complex FFT per CHANNEL PAIR (f_{2p} + i f_{2p+1}).
__global__ __launch_bounds__(256) void filtfft_kernel() {
    extern __shared__ float2 smf[];
    float2* F  = smf;                 // swizzled, 4224
    float2* TW = smf + A_ELEMS;       // swizzled, 2112
    int pb = blockIdx.x, tid = threadIdx.x;  // 256 threads, 256 blocks
    int c0 = 2 * pb;
    make_tw(TW);
    __syncthreads();
    for (int i = tid; i < NFFT; i += 256) {
        int r = dr4(i);
        float v0 = 0.f, v1 = 0.f;
        if (r < LSEQ) { v0 = g_filt[r * DMODEL + c0]; v1 = g_filt[r * DMODEL + c0 + 1]; }
        F[IDX(i)] = make_float2(v0, v1);
    }
    fft4096_r16(F, TW);
    float2* Gp = g_Ff + (size_t)pb * NFFT;
    for (int t = tid; t < NFFT; t += 256) Gp[t] = F[IDX(t)];
}

// Causal conv via FFT: z = k_norm + i*v_norm per channel; filter spectrum
// reconstructed on the fly from the packed pair spectrum (conjugate symmetry).
__global__ __launch_bounds__(256) void fftconv_kernel() {
    extern __shared__ float2 smf[];
    float2* Z  = smf;                 // swizzled, 4224
    float2* TW = smf + A_ELEMS;       // swizzled, 2112
    int c = blockIdx.x, tid = threadIdx.x;  // 256 threads, 512 blocks
    make_tw(TW);
    __syncthreads();
    for (int i = tid; i < NFFT; i += 256) {
        int r = dr4(i);
        float kr = 0.f, vi = 0.f;
        if (r < LSEQ) { kr = g_k[r * DMODEL + c]; vi = g_v[r * DMODEL + c]; }
        Z[IDX(i)] = make_float2(kr, vi);
    }
    fft4096_r16(Z, TW);
    const float2* Gp = g_Ff + (size_t)(c >> 1) * NFFT;
    int par = c & 1;
    float2 y[16];
#pragma unroll
    for (int jj = 0; jj < 16; jj++) {
        int t = tid + jj * 256;
        float2 Gt = Gp[t];
        float2 Gr = Gp[(NFFT - t) & (NFFT - 1)];
        float Ax = 0.5f * (Gt.x + Gr.x), Ay = 0.5f * (Gt.y - Gr.y);
        float Dx = 0.5f * (Gt.x - Gr.x), Dy = 0.5f * (Gt.y + Gr.y);
        float Fx = par ? Dy : Ax;
        float Fy = par ? -Dx : Ay;
        float2 z = Z[IDX(t)];
        float pr = z.x * Fx - z.y * Fy;
        float pi = z.x * Fy + z.y * Fx;
        y[jj] = make_float2(pr, -pi);   // conj for IFFT-via-FFT
    }
    __syncthreads();
#pragma unroll
    for (int jj = 0; jj < 16; jj++) {
        int i = tid + jj * 256;
        Z[IDX(dr4(i))] = y[jj];
    }
    fft4096_r16(Z, TW);
    const float invN = 1.f / (float)NFFT;
    for (int t = tid; t < LSEQ; t += 256) {
        float2 w = Z[IDX(t)];
        g_kf[t * DMODEL + c] =  w.x * invN;   // Re(conj) = Re
        g_vf[t * DMODEL + c] = -w.y * invN;   // Im(conj) = -Im
    }
}

// ---------------- gates: g_l = relu(v_f^T (W .* scale) k_f + b)^2 + eps ----------------
// 32 positions per block; k/v rows staged into smem with coalesced float4 loads,
// then each warp computes 4 positions entirely from LDS (broadcast, conflict-free).
__global__ __launch_bounds__(256) void gates_kernel(const float* __restrict__ wgz_w,
                                                    const float* __restrict__ wgz_b,
                                                    const float* __restrict__ scale) {
    __shared__ float Wsc[HD * HD];
    __shared__ float ks[32][HD];
    __shared__ float vs[32][HD];
    int tid = threadIdx.x;  // 256
    for (int i = tid; i < HD * HD; i += 256) Wsc[i] = wgz_w[i] * scale[i];
    int pb = blockIdx.x * 32;             // 32 consecutive p = h*2048+l, same head
    int h = pb >> 11, lbase = pb & (LSEQ - 1);
    // coalesced tile load: 32 rows x 64 cols = 512 float4
    {
        int r4 = tid >> 4, c4 = (tid & 15) * 4;    // 16 rows per pass, 2 passes
#pragma unroll
        for (int pass = 0; pass < 2; pass++) {
            int row = r4 + pass * 16;
            size_t ga = (size_t)(lbase + row) * DMODEL + h * HD + c4;
            *reinterpret_cast<float4*>(&ks[row][c4]) = *reinterpret_cast<const float4*>(g_kf + ga);
            *reinterpret_cast<float4*>(&vs[row][c4]) = *reinterpret_cast<const float4*>(g_vf + ga);
        }
    }
    __syncthreads();
    int w = tid >> 5, lane = tid & 31;
    int i0 = w * 4;                        // 4 positions per warp
    float aA0 = 0.f, aA1 = 0.f, aA2 = 0.f, aA3 = 0.f;
    float aB0 = 0.f, aB1 = 0.f, aB2 = 0.f, aB3 = 0.f;
#pragma unroll 8
    for (int d = 0; d < HD; d++) {
        float w0 = Wsc[d * 64 + lane];
        float w1 = Wsc[d * 64 + lane + 32];
        float v0 = vs[i0 + 0][d], v1 = vs[i0 + 1][d], v2 = vs[i0 + 2][d], v3 = vs[i0 + 3][d];
        aA0 += v0 * w0; aB0 += v0 * w1;
        aA1 += v1 * w0; aB1 += v1 * w1;
        aA2 += v2 * w0; aB2 += v2 * w1;
        aA3 += v3 * w0; aB3 += v3 * w1;
    }
    float p0 = aA0 * ks[i0 + 0][lane] + aB0 * ks[i0 + 0][lane + 32];
    float p1 = aA1 * ks[i0 + 1][lane] + aB1 * ks[i0 + 1][lane + 32];
    float p2 = aA2 * ks[i0 + 2][lane] + aB2 * ks[i0 + 2][lane + 32];
    float p3 = aA3 * ks[i0 + 3][lane] + aB3 * ks[i0 + 3][lane + 32];
#pragma unroll
    for (int o = 16; o; o >>= 1) {
        p0 += __shfl_xor_sync(0xffffffffu, p0, o);
        p1 += __shfl_xor_sync(0xffffffffu, p1, o);
        p2 += __shfl_xor_sync(0xffffffffu, p2, o);
        p3 += __shfl_xor_sync(0xffffffffu, p3, o);
    }
    if (lane < 4) {
        float pj = (lane == 0) ? p0 : (lane == 1) ? p1 : (lane == 2) ? p2 : p3;
        float r = fmaxf(pj + wgz_b[0], 0.f);
        g_gate[pb + i0 + lane] = r * r + EPSF;
    }
}

// ---------------- per-chunk rank-1 sums: S_c[d,e] = sum_{l in chunk} g_l v_f[l,d] k_f[l,e] ----
// 256 threads: 4 threads per column e, 16 d-values each.
__global__ __launch_bounds__(256) void chunksum_kernel() {
    int hb = blockIdx.x;                  // h*16 + c
    int h = hb >> 4, c = hb & 15;
    int tid = threadIdx.x;                // 256
    int e = tid >> 2, quarter = tid & 3, d0 = quarter * 16;
    float acc[16];
#pragma unroll
    for (int j = 0; j < 16; j++) acc[j] = 0.f;
    int l0 = c * TCH;
    for (int i = 0; i < TCH; i++) {
        int l = l0 + i;
        float gg = g_gate[h * LSEQ + l];
        float ke = g_kf[l * DMODEL + h * HD + e];
        float gk = gg * ke;
        const float4* vp = reinterpret_cast<const float4*>(g_vf + l * DMODEL + h * HD + d0);
#pragma unroll
        for (int j4 = 0; j4 < 4; j4++) {
            float4 v4 = vp[j4];
            acc[j4 * 4 + 0] += gk * v4.x;
            acc[j4 * 4 + 1] += gk * v4.y;
            acc[j4 * 4 + 2] += gk * v4.z;
            acc[j4 * 4 + 3] += gk * v4.w;
        }
    }
    float* Sp = g_S + (size_t)hb * HD * HD;
#pragma unroll
    for (int j = 0; j < 16; j++) Sp[(d0 + j) * 64 + e] = acc[j];
}

// ---------------- exclusive prefix over chunks (state matrices + gate sums) ----------------
__global__ void prefix_kernel() {
    int h = blockIdx.x, tid = threadIdx.x;  // 512
    __shared__ float gc[NCHUNK];
    if (tid < NCHUNK) {
        float s = 0.f;
        for (int i = 0; i < TCH; i++) s += g_gate[h * LSEQ + tid * TCH + i];
        gc[tid] = s;
    }
    __syncthreads();
    if (tid == 0) {
        float run = 0.f;
        for (int c = 0; c < NCHUNK; c++) { float t = gc[c]; g_Gpre[h * NCHUNK + c] = run; run += t; }
    }
    for (int idx = tid; idx < HD * HD; idx += 512) {
        float run = 0.f;
#pragma unroll
        for (int c = 0; c < NCHUNK; c++) {
            size_t off = ((size_t)(h * NCHUNK + c)) * HD * HD + idx;
            float t = g_S[off];
            g_Spre[off] = run;
            run += t;
        }
    }
}

// ---------------- intra-chunk scan + readout + fused L2 norm ----------------
// 256 threads: 4 threads per column e. Results staged in smem, normalized in epilogue.
__global__ __launch_bounds__(256) void scan_readout_kernel(const float* __restrict__ scale) {
    extern __shared__ float sm[];
    float* qs = sm;                      // 128*64
    float* ks = sm + TCH * HD;
    float* vs = sm + 2 * TCH * HD;
    float* os = sm + 3 * TCH * HD;       // 128*64 output staging
    float* gs = sm + 4 * TCH * HD;       // 128
    int hb = blockIdx.x;
    int h = hb >> 4, c = hb & 15;
    int tid = threadIdx.x;               // 256
    int l0 = c * TCH;
    for (int idx = tid; idx < TCH * HD; idx += 256) {
        int row = idx >> 6, col = idx & 63;
        int ga = (l0 + row) * DMODEL + h * HD + col;
        qs[idx] = g_q[ga];
        ks[idx] = g_kf[ga];
        vs[idx] = g_vf[ga];
    }
    if (tid < TCH) gs[tid] = g_gate[h * LSEQ + l0 + tid];
    int e = tid >> 2, quarter = tid & 3, d0 = quarter * 16;
    float M[16], sc[16];
    {
        const float* Sp = g_Spre + (size_t)hb * HD * HD;
#pragma unroll
        for (int j = 0; j < 16; j++) {
            M[j]  = Sp[(d0 + j) * 64 + e];
            sc[j] = scale[(d0 + j) * 64 + e];
        }
    }
    float G = g_Gpre[h * NCHUNK + c];
    __syncthreads();
    const float4* q4 = reinterpret_cast<const float4*>(qs);
    const float4* v4 = reinterpret_cast<const float4*>(vs);
    int o4 = quarter * 4;
    for (int i = 0; i < TCH; i++) {
        float gg = gs[i]; G += gg;
        float ke = ks[i * HD + e];
        float gk = gg * ke;
        float r = 0.f;
#pragma unroll
        for (int j4 = 0; j4 < 4; j4++) {
            float4 vv = v4[i * 16 + o4 + j4];
            float4 qq = q4[i * 16 + o4 + j4];
            int jb = j4 * 4;
            M[jb + 0] += gk * vv.x; r += qq.x * (sc[jb + 0] * M[jb + 0]);
            M[jb + 1] += gk * vv.y; r += qq.y * (sc[jb + 1] * M[jb + 1]);
            M[jb + 2] += gk * vv.z; r += qq.z * (sc[jb + 2] * M[jb + 2]);
            M[jb + 3] += gk * vv.w; r += qq.w * (sc[jb + 3] * M[jb + 3]);
        }
        r += __shfl_xor_sync(0xffffffffu, r, 1);
        r += __shfl_xor_sync(0xffffffffu, r, 2);
        if (quarter == 0) os[i * HD + e] = r / fmaxf(G, EPSF);
    }
    __syncthreads();
    // epilogue: per-position L2 norm (identical math to the old spnorm kernel)
    {
        int w = tid >> 5, lane = tid & 31;
        for (int i = w; i < TCH; i += 8) {
            float a = os[i * HD + lane], b = os[i * HD + lane + 32];
            float ss = a * a + b * b;
#pragma unroll
            for (int o = 16; o; o >>= 1) ss += __shfl_xor_sync(0xffffffffu, ss, o);
            float inv = 1.f / fmaxf(sqrtf(ss), EPSF);
            float* outp = g_sraw + (size_t)(l0 + i) * DMODEL + h * HD;
            outp[lane] = a * inv;
            outp[lane + 32] = b * inv;
        }
    }
}
#define SR_SMEM ((4 * TCH * HD + TCH) * 4)

// ---------------- launch ----------------
extern "C" void kernel_launch(void* const* d_in, const int* in_sizes, int n_in,
                              void* d_out, int out_size) {
    const float* x     = (const float*)d_in[0];
    const float* sb    = (const float*)d_in[1];
    const float* wq_w  = (const float*)d_in[2];
    const float* wq_b  = (const float*)d_in[3];
    const float* wk_w  = (const float*)d_in[4];
    const float* wk_b  = (const float*)d_in[5];
    const float* wv_w  = (const float*)d_in[6];
    const float* wv_b  = (const float*)d_in[7];
    const float* wo_w  = (const float*)d_in[8];
    const float* wo_b  = (const float*)d_in[9];
    const float* td_w  = (const float*)d_in[10];
    const float* td_b  = (const float*)d_in[11];
    const float* wgz_w = (const float*)d_in[12];
    const float* wgz_b = (const float*)d_in[13];
    const float* kvs   = (const float*)d_in[14];
    float* out = (float*)d_out;

    float* sp;
    cudaGetSymbolAddress((void**)&sp, g_sraw);

    cudaFuncSetAttribute(filtfft_kernel, cudaFuncAttributeMaxDynamicSharedMemorySize, FFT_SMEM);
    cudaFuncSetAttribute(fftconv_kernel, cudaFuncAttributeMaxDynamicSharedMemorySize, FFT_SMEM);
    cudaFuncSetAttribute(scan_readout_kernel, cudaFuncAttributeMaxDynamicSharedMemorySize, SR_SMEM);

    dim3 g4(DMODEL / 64, LSEQ / 64, 4);
    gemm4_kernel<<<g4, 256>>>(x, sb, wq_w, wk_w, wv_w, td_w, wq_b, wk_b, wv_b, td_b);
    filtfft_kernel<<<DMODEL / 2, 256, FFT_SMEM>>>();
    fftconv_kernel<<<DMODEL, 256, FFT_SMEM>>>();
    gates_kernel<<<(NH * LSEQ) / 32, 256>>>(wgz_w, wgz_b, kvs);
    chunksum_kernel<<<NH * NCHUNK, 256>>>();
    prefix_kernel<<<NH, 512>>>();
    scan_readout_kernel<<<NH * NCHUNK, 256, SR_SMEM>>>(kvs);
    dim3 g1(DMODEL / 64, LSEQ / 64, 1);
    gemm1_kernel<<<g1, 256>>>(sp, wo_w, wo_b, out);
}

// round 16
// speedup vs baseline: 1.5722x; 1.0941x over previous
#include <cuda_runtime.h>
#include <math.h>

#define LSEQ 2048
#define DMODEL 512
#define NH 8
#define HD 64
#define NFFT 4096
#define EPSF 1e-5f
#define NCHUNK 16
#define TCH 128

typedef unsigned long long u64;

// ---------------- scratch (device globals; no runtime allocation) ----------------
// Layout note: g_k, g_v, g_filt, g_kf, g_vf are CHANNEL-MAJOR [DMODEL][LSEQ].
// g_q, g_sraw stay row-major [LSEQ][DMODEL].
__device__ float g_q[LSEQ * DMODEL];
__device__ float g_k[DMODEL * LSEQ];
__device__ float g_v[DMODEL * LSEQ];
__device__ float g_filt[DMODEL * LSEQ];
__device__ float g_kf[DMODEL * LSEQ];
__device__ float g_vf[DMODEL * LSEQ];
__device__ float g_gate[NH * LSEQ];
__device__ float g_S[NH * NCHUNK * HD * HD];
__device__ float g_Spre[NH * NCHUNK * HD * HD];
__device__ float g_Gpre[NH * NCHUNK];
__device__ float g_sraw[LSEQ * DMODEL];
__device__ float2 g_Ff[(DMODEL / 2) * NFFT];   // packed filter spectra (2 channels/FFT)

// ---------------- packed f32x2 helpers (sm_103a FFMA2 path) ----------------
__device__ __forceinline__ u64 pk2(float v) {
    u64 r; asm("mov.b64 %0, {%1, %1};" : "=l"(r) : "f"(v)); return r;
}
__device__ __forceinline__ void upk2(u64 v, float& lo, float& hi) {
    asm("mov.b64 {%0, %1}, %2;" : "=f"(lo), "=f"(hi) : "l"(v));
}
__device__ __forceinline__ u64 ffma2(u64 a, u64 b, u64 c) {
    u64 d; asm("fma.rn.f32x2 %0, %1, %2, %3;" : "=l"(d) : "l"(a), "l"(b), "l"(c)); return d;
}

// ---------------- double-buffered GEMM body: C = A.W^T + bias -------------------
// 64x64 tile, 256 threads, 4x4 acc (packed f32x2), K=N=512 fixed.
// l2n: L2-normalize each 64-wide output row segment (N-tile == one head).
// trans: store output transposed (C is [DMODEL][LSEQ]) via smem staging.
__device__ __forceinline__ void gemm_body(const float* __restrict__ A, const float* __restrict__ W,
                                          const float* __restrict__ bias, float* __restrict__ C,
                                          int l2n, int trans) {
    __shared__ __align__(16) float As[2][16][68];
    __shared__ __align__(16) float Ws[2][16][68];
    int tid = threadIdx.x;                 // 256 threads
    int bm = blockIdx.y * 64, bn = blockIdx.x * 64;
    int row = tid >> 2, kc = (tid & 3) << 2;
    int tx = tid & 15, ty = tid >> 4;
    const float* Ap = A + (size_t)(bm + row) * DMODEL + kc;
    const float* Wp = W + (size_t)(bn + row) * DMODEL + kc;

    u64 acc2[4][2];
#pragma unroll
    for (int i = 0; i < 4; i++) { acc2[i][0] = 0ull; acc2[i][1] = 0ull; }

    {
        float4 a4 = *reinterpret_cast<const float4*>(Ap);
        float4 w4 = *reinterpret_cast<const float4*>(Wp);
        As[0][kc + 0][row] = a4.x; As[0][kc + 1][row] = a4.y; As[0][kc + 2][row] = a4.z; As[0][kc + 3][row] = a4.w;
        Ws[0][kc + 0][row] = w4.x; Ws[0][kc + 1][row] = w4.y; Ws[0][kc + 2][row] = w4.z; Ws[0][kc + 3][row] = w4.w;
    }
    __syncthreads();

    int buf = 0;
    for (int k0 = 16; k0 <= DMODEL; k0 += 16) {
        float4 a4n, w4n;
        bool more = (k0 < DMODEL);
        if (more) {
            a4n = *reinterpret_cast<const float4*>(Ap + k0);
            w4n = *reinterpret_cast<const float4*>(Wp + k0);
        }
#pragma unroll
        for (int kk = 0; kk < 16; kk++) {
            const u64* bp = reinterpret_cast<const u64*>(&Ws[buf][kk][tx * 4]);
            u64 b0 = bp[0], b1 = bp[1];
#pragma unroll
            for (int i = 0; i < 4; i++) {
                u64 ap = pk2(As[buf][kk][ty * 4 + i]);
                acc2[i][0] = ffma2(ap, b0, acc2[i][0]);
                acc2[i][1] = ffma2(ap, b1, acc2[i][1]);
            }
        }
        if (more) {
            int nb = buf ^ 1;
            As[nb][kc + 0][row] = a4n.x; As[nb][kc + 1][row] = a4n.y; As[nb][kc + 2][row] = a4n.z; As[nb][kc + 3][row] = a4n.w;
            Ws[nb][kc + 0][row] = w4n.x; Ws[nb][kc + 1][row] = w4n.y; Ws[nb][kc + 2][row] = w4n.z; Ws[nb][kc + 3][row] = w4n.w;
            __syncthreads();
        }
        buf ^= 1;
    }
    float4 bb = *reinterpret_cast<const float4*>(bias + bn + tx * 4);

    if (trans) __syncthreads();   // done reading As/Ws; they become the transpose buffer
    float* T0 = &As[0][0][0];     // rows 0..31 of T (stride 65): 32*65=2080 <= 2176
    float* T1 = &Ws[0][0][0];     // rows 32..63

#pragma unroll
    for (int i = 0; i < 4; i++) {
        float c0, c1, c2, c3;
        upk2(acc2[i][0], c0, c1);
        upk2(acc2[i][1], c2, c3);
        c0 += bb.x; c1 += bb.y; c2 += bb.z; c3 += bb.w;
        if (l2n) {
            float ss = c0 * c0 + c1 * c1 + c2 * c2 + c3 * c3;
            ss += __shfl_xor_sync(0xffffffffu, ss, 1);
            ss += __shfl_xor_sync(0xffffffffu, ss, 2);
            ss += __shfl_xor_sync(0xffffffffu, ss, 4);
            ss += __shfl_xor_sync(0xffffffffu, ss, 8);
            float inv = 1.f / fmaxf(sqrtf(ss), EPSF);
            c0 *= inv; c1 *= inv; c2 *= inv; c3 *= inv;
        }
        if (!trans) {
            *reinterpret_cast<float4*>(C + (size_t)(bm + ty * 4 + i) * DMODEL + bn + tx * 4)
                = make_float4(c0, c1, c2, c3);
        } else {
            int m = ty * 4 + i;
            float cv[4] = {c0, c1, c2, c3};
#pragma unroll
            for (int j = 0; j < 4; j++) {
                int n = tx * 4 + j;
                float* Tp = (n < 32 ? T0 : T1) + (n & 31) * 65 + m;
                *Tp = cv[j];
            }
        }
    }
    if (trans) {
        __syncthreads();
#pragma unroll
        for (int rep = 0; rep < 4; rep++) {
            int idx = rep * 256 + tid;
            int n = idx >> 4, mf = idx & 15;
            const float* Tp = (n < 32 ? T0 : T1) + (n & 31) * 65 + mf * 4;
            float4 o = make_float4(Tp[0], Tp[1], Tp[2], Tp[3]);
            *reinterpret_cast<float4*>(C + (size_t)(bn + n) * LSEQ + bm + mf * 4) = o;
        }
    }
}

// fused Q/K/V/filter projections: blockIdx.z selects the GEMM (1024 blocks total)
__global__ __launch_bounds__(256) void gemm4_kernel(
    const float* __restrict__ x, const float* __restrict__ sb,
    const float* __restrict__ Wq, const float* __restrict__ Wk,
    const float* __restrict__ Wv, const float* __restrict__ Wt,
    const float* __restrict__ bq, const float* __restrict__ bk,
    const float* __restrict__ bv, const float* __restrict__ bt) {
    int z = blockIdx.z;
    const float* A = (z == 3) ? sb : x;
    const float* W = (z == 0) ? Wq : (z == 1) ? Wk : (z == 2) ? Wv : Wt;
    const float* b = (z == 0) ? bq : (z == 1) ? bk : (z == 2) ? bv : bt;
    float* C = (z == 0) ? g_q : (z == 1) ? g_k : (z == 2) ? g_v : g_filt;
    gemm_body(A, W, b, C, (z == 1 || z == 2) ? 1 : 0, (z != 0) ? 1 : 0);
}

__global__ __launch_bounds__(256) void gemm1_kernel(const float* __restrict__ A, const float* __restrict__ W,
                                                    const float* __restrict__ bias, float* __restrict__ C) {
    gemm_body(A, W, bias, C, 0, 0);
}

// ---------------- FFT over 4096 complex points: 3 register-resident radix-16 super-stages
#define IDX(i) ((i) + ((i) >> 5))
#define A_ELEMS (NFFT + NFFT / 32)                 // 4224 float2
#define TW_ELEMS (NFFT / 2 + NFFT / 64)            // 2112 float2
#define FFT_SMEM ((A_ELEMS + TW_ELEMS) * 8)        // 50688 bytes

__device__ __forceinline__ float2 cmul(float2 a, float2 b) {
    return make_float2(a.x * b.x - a.y * b.y, a.x * b.y + a.y * b.x);
}

// base-4 digit reversal of a 12-bit index
__device__ __forceinline__ int dr4(int i) {
    int r = __brev(i) >> 20;
    return ((r & 0x555) << 1) | ((r >> 1) & 0x555);
}

__device__ __forceinline__ void bfly4(float2& a0, float2& a1, float2& a2, float2& a3,
                                      float2 w1, float2 w2, float2 w3) {
    float2 t1 = cmul(a1, w1);
    float2 t2 = cmul(a2, w2);
    float2 t3 = cmul(a3, w3);
    float u0x = a0.x + t2.x, u0y = a0.y + t2.y;
    float u1x = a0.x - t2.x, u1y = a0.y - t2.y;
    float u2x = t1.x + t3.x, u2y = t1.y + t3.y;
    float u3x = t1.x - t3.x, u3y = t1.y - t3.y;
    a0 = make_float2(u0x + u2x, u0y + u2y);
    a1 = make_float2(u1x + u3y, u1y - u3x);   // u1 - i*u3
    a2 = make_float2(u0x - u2x, u0y - u2y);
    a3 = make_float2(u1x - u3y, u1y + u3x);   // u1 + i*u3
}

__device__ __forceinline__ void fft4096_r16(float2* A, const float2* TW) {
    int g = threadIdx.x;   // 256 groups of 16 points
#pragma unroll
    for (int t = 0; t < 3; t++) {
        __syncthreads();
        const int fourt = 4 * t;
        const int L = 1 << fourt;
        const int p = g & (L - 1);
        const int base = ((g >> fourt) << (fourt + 4)) + p;
        const int sh = 10 - fourt;
        float2 x[16];
#pragma unroll
        for (int q = 0; q < 16; q++) x[q] = A[IDX(base + (q << fourt))];
        {
            float2 w1 = TW[IDX(p << sh)];
            float2 w2 = TW[IDX((p << sh) << 1)];
            float2 w3 = cmul(w1, w2);
#pragma unroll
            for (int r = 0; r < 4; r++)
                bfly4(x[4 * r], x[4 * r + 1], x[4 * r + 2], x[4 * r + 3], w1, w2, w3);
        }
#pragma unroll
        for (int q0 = 0; q0 < 4; q0++) {
            int idx = (p + (q0 << fourt)) << (sh - 2);
            float2 w1 = TW[IDX(idx)];
            float2 w2 = TW[IDX(idx << 1)];
            float2 w3 = cmul(w1, w2);
            bfly4(x[q0], x[q0 + 4], x[q0 + 8], x[q0 + 12], w1, w2, w3);
        }
#pragma unroll
        for (int q = 0; q < 16; q++) A[IDX(base + (q << fourt))] = x[q];
    }
    __syncthreads();
}

__device__ __forceinline__ void make_tw(float2* TW) {
    for (int t = threadIdx.x; t < NFFT / 2; t += 256) {
        float s, co;
        __sincosf(-6.283185307179586f * (float)t / (float)NFFT, &s, &co);
        TW[IDX(t)] = make_float2(co, s);
    }
}

// Precompute filter spectra: one complex FFT per CHANNEL PAIR (f_{2p} + i f_{2p+1}).
// Inputs channel-major: coalesced float4 loads + smem bit-reversal scatter.
__global__ __launch_bounds__(256) void filtfft_kernel() {
    extern __shared__ float2 smf[];
    float2* F  = smf;                 // swizzled, 4224
    float2* TW = smf + A_ELEMS;       // swizzled, 2112
    int pb = blockIdx.x, tid = threadIdx.x;  // 256 threads, 256 blocks
    int c0 = 2 * pb;
    make_tw(TW);
    for (int idx = tid; idx < NFFT / 4; idx += 256) {
        int l = idx * 4;
        float4 f0 = make_float4(0.f, 0.f, 0.f, 0.f), f1 = f0;
        if (l < LSEQ) {
            f0 = *reinterpret_cast<const float4*>(g_filt + (size_t)c0 * LSEQ + l);
            f1 = *reinterpret_cast<const float4*>(g_filt + (size_t)(c0 + 1) * LSEQ + l);
        }
        float a0[4] = {f0.x, f0.y, f0.z, f0.w};
        float a1[4] = {f1.x, f1.y, f1.z, f1.w};
#pragma unroll
        for (int j = 0; j < 4; j++) F[IDX(dr4(l + j))] = make_float2(a0[j], a1[j]);
    }
    fft4096_r16(F, TW);
    float2* Gp = g_Ff + (size_t)pb * NFFT;
    for (int t = tid; t < NFFT; t += 256) Gp[t] = F[IDX(t)];
}

// Causal conv via FFT: z = k_norm + i*v_norm per channel; filter spectrum
// reconstructed on the fly from the packed pair spectrum (conjugate symmetry).
// Channel-major I/O: fully coalesced global, scatter happens in smem.
__global__ __launch_bounds__(256) void fftconv_kernel() {
    extern __shared__ float2 smf[];
    float2* Z  = smf;                 // swizzled, 4224
    float2* TW = smf + A_ELEMS;       // swizzled, 2112
    int c = blockIdx.x, tid = threadIdx.x;  // 256 threads, 512 blocks
    make_tw(TW);
    for (int idx = tid; idx < NFFT / 4; idx += 256) {
        int l = idx * 4;
        float4 k4 = make_float4(0.f, 0.f, 0.f, 0.f), v4 = k4;
        if (l < LSEQ) {
            k4 = *reinterpret_cast<const float4*>(g_k + (size_t)c * LSEQ + l);
            v4 = *reinterpret_cast<const float4*>(g_v + (size_t)c * LSEQ + l);
        }
        float kk[4] = {k4.x, k4.y, k4.z, k4.w};
        float vv[4] = {v4.x, v4.y, v4.z, v4.w};
#pragma unroll
        for (int j = 0; j < 4; j++) Z[IDX(dr4(l + j))] = make_float2(kk[j], vv[j]);
    }
    fft4096_r16(Z, TW);
    const float2* Gp = g_Ff + (size_t)(c >> 1) * NFFT;
    int par = c & 1;
    float2 y[16];
#pragma unroll
    for (int jj = 0; jj < 16; jj++) {
        int t = tid + jj * 256;
        float2 Gt = Gp[t];
        float2 Gr = Gp[(NFFT - t) & (NFFT - 1)];
        float Ax = 0.5f * (Gt.x + Gr.x), Ay = 0.5f * (Gt.y - Gr.y);
        float Dx = 0.5f * (Gt.x - Gr.x), Dy = 0.5f * (Gt.y + Gr.y);
        float Fx = par ? Dy : Ax;
        float Fy = par ? -Dx : Ay;
        float2 z = Z[IDX(t)];
        float pr = z.x * Fx - z.y * Fy;
        float pi = z.x * Fy + z.y * Fx;
        y[jj] = make_float2(pr, -pi);   // conj for IFFT-via-FFT
    }
    __syncthreads();
#pragma unroll
    for (int jj = 0; jj < 16; jj++) {
        int i = tid + jj * 256;
        Z[IDX(dr4(i))] = y[jj];
    }
    fft4096_r16(Z, TW);
    const float invN = 1.f / (float)NFFT;
    for (int t = tid; t < LSEQ; t += 256) {
        float2 w = Z[IDX(t)];
        g_kf[(size_t)c * LSEQ + t] =  w.x * invN;   // Re(conj) = Re
        g_vf[(size_t)c * LSEQ + t] = -w.y * invN;   // Im(conj) = -Im
    }
}

// ---------------- transposed tile fill helper: [D][L] global -> [l][68] smem ---------
// 128 l x 64 ch tile. 4-row x 8-float4 per-warp pattern (coalesced global, ~4-way smem).
__device__ __forceinline__ void fill_tile_T(float* dst, const float* __restrict__ src,
                                            int chbase, int l0, int tid) {
    for (int idx = tid; idx < 2048; idx += 256) {
        int ch = ((idx >> 3) & 3) + ((idx >> 5) & 15) * 4;
        int lf = (idx & 7) + (idx >> 9) * 8;
        float4 a = *reinterpret_cast<const float4*>(src + (size_t)(chbase + ch) * LSEQ + l0 + lf * 4);
        float av[4] = {a.x, a.y, a.z, a.w};
#pragma unroll
        for (int j = 0; j < 4; j++) dst[(lf * 4 + j) * 68 + ch] = av[j];
    }
}

// ---------------- gates: g_l = relu(v_f^T (W .* scale) k_f + b)^2 + eps ----------------
// 128 positions per block (grid 128): weights read once per block, tiles smem-staged.
__global__ __launch_bounds__(256) void gates_kernel(const float* __restrict__ wgz_w,
                                                    const float* __restrict__ wgz_b,
                                                    const float* __restrict__ scale) {
    extern __shared__ float sg[];
    float* Wsc = sg;                  // 4096
    float* ks  = sg + 4096;           // 128*68
    float* vs  = sg + 4096 + 128 * 68;
    int tid = threadIdx.x;  // 256
    int h = blockIdx.x >> 4, l0 = (blockIdx.x & 15) * 128;
    for (int i = tid; i < HD * HD; i += 256) Wsc[i] = wgz_w[i] * scale[i];
    fill_tile_T(ks, g_kf, h * HD, l0, tid);
    fill_tile_T(vs, g_vf, h * HD, l0, tid);
    __syncthreads();
    int w = tid >> 5, lane = tid & 31;
    float bias0 = wgz_b[0];
#pragma unroll
    for (int g4 = 0; g4 < 4; g4++) {
        int i0 = w * 16 + g4 * 4;
        float aA0 = 0.f, aA1 = 0.f, aA2 = 0.f, aA3 = 0.f;
        float aB0 = 0.f, aB1 = 0.f, aB2 = 0.f, aB3 = 0.f;
#pragma unroll 8
        for (int d = 0; d < HD; d++) {
            float w0 = Wsc[d * 64 + lane];
            float w1 = Wsc[d * 64 + lane + 32];
            float v0 = vs[(i0 + 0) * 68 + d], v1 = vs[(i0 + 1) * 68 + d];
            float v2 = vs[(i0 + 2) * 68 + d], v3 = vs[(i0 + 3) * 68 + d];
            aA0 += v0 * w0; aB0 += v0 * w1;
            aA1 += v1 * w0; aB1 += v1 * w1;
            aA2 += v2 * w0; aB2 += v2 * w1;
            aA3 += v3 * w0; aB3 += v3 * w1;
        }
        float p0 = aA0 * ks[(i0 + 0) * 68 + lane] + aB0 * ks[(i0 + 0) * 68 + lane + 32];
        float p1 = aA1 * ks[(i0 + 1) * 68 + lane] + aB1 * ks[(i0 + 1) * 68 + lane + 32];
        float p2 = aA2 * ks[(i0 + 2) * 68 + lane] + aB2 * ks[(i0 + 2) * 68 + lane + 32];
        float p3 = aA3 * ks[(i0 + 3) * 68 + lane] + aB3 * ks[(i0 + 3) * 68 + lane + 32];
#pragma unroll
        for (int o = 16; o; o >>= 1) {
            p0 += __shfl_xor_sync(0xffffffffu, p0, o);
            p1 += __shfl_xor_sync(0xffffffffu, p1, o);
            p2 += __shfl_xor_sync(0xffffffffu, p2, o);
            p3 += __shfl_xor_sync(0xffffffffu, p3, o);
        }
        if (lane < 4) {
            float pj = (lane == 0) ? p0 : (lane == 1) ? p1 : (lane == 2) ? p2 : p3;
            float r = fmaxf(pj + bias0, 0.f);
            g_gate[h * LSEQ + l0 + i0 + lane] = r * r + EPSF;
        }
    }
}
#define GT_SMEM ((4096 + 2 * 128 * 68) * 4)

// ---------------- per-chunk rank-1 sums: S_c[d,e] = sum_l g_l v[d,l] k[e,l] -----------
// Channel-major smem [ch][132]; dot-products along l (float4). Fully coalesced fills.
__global__ __launch_bounds__(256) void chunksum_kernel() {
    extern __shared__ float scm[];
    float* ks  = scm;                 // 64*132
    float* vs  = scm + 64 * 132;
    float* gsm = scm + 2 * 64 * 132;  // 128
    int hb = blockIdx.x;              // h*16 + c
    int h = hb >> 4, c = hb & 15;
    int tid = threadIdx.x;            // 256
    int l0 = c * TCH;
    for (int idx = tid; idx < 2048; idx += 256) {
        int ch = idx >> 5, l4 = idx & 31;
        *reinterpret_cast<float4*>(&ks[ch * 132 + l4 * 4]) =
            *reinterpret_cast<const float4*>(g_kf + (size_t)(h * HD + ch) * LSEQ + l0 + l4 * 4);
        *reinterpret_cast<float4*>(&vs[ch * 132 + l4 * 4]) =
            *reinterpret_cast<const float4*>(g_vf + (size_t)(h * HD + ch) * LSEQ + l0 + l4 * 4);
    }
    if (tid < TCH) gsm[tid] = g_gate[h * LSEQ + l0 + tid];
    __syncthreads();
    int e = tid >> 2, quarter = tid & 3, d0 = quarter * 16;
    float acc[16];
#pragma unroll
    for (int j = 0; j < 16; j++) acc[j] = 0.f;
    for (int l4 = 0; l4 < 32; l4++) {
        float4 k4 = *reinterpret_cast<const float4*>(&ks[e * 132 + l4 * 4]);
        float4 g4 = *reinterpret_cast<const float4*>(&gsm[l4 * 4]);
        float4 gk = make_float4(g4.x * k4.x, g4.y * k4.y, g4.z * k4.z, g4.w * k4.w);
#pragma unroll
        for (int dd = 0; dd < 16; dd++) {
            float4 v4 = *reinterpret_cast<const float4*>(&vs[(d0 + dd) * 132 + l4 * 4]);
            acc[dd] += gk.x * v4.x + gk.y * v4.y + gk.z * v4.z + gk.w * v4.w;
        }
    }
    float* Sp = g_S + (size_t)hb * HD * HD;
#pragma unroll
    for (int dd = 0; dd < 16; dd++) Sp[(d0 + dd) * 64 + e] = acc[dd];
}
#define CS_SMEM ((2 * 64 * 132 + 128) * 4)

// ---------------- exclusive prefix over chunks (state matrices + gate sums) ----------------
__global__ void prefix_kernel() {
    int h = blockIdx.x, tid = threadIdx.x;  // 512
    __shared__ float gc[NCHUNK];
    if (tid < NCHUNK) {
        float s = 0.f;
        for (int i = 0; i < TCH; i++) s += g_gate[h * LSEQ + tid * TCH + i];
        gc[tid] = s;
    }
    __syncthreads();
    if (tid == 0) {
        float run = 0.f;
        for (int c = 0; c < NCHUNK; c++) { float t = gc[c]; g_Gpre[h * NCHUNK + c] = run; run += t; }
    }
    for (int idx = tid; idx < HD * HD; idx += 512) {
        float run = 0.f;
#pragma unroll
        for (int c = 0; c < NCHUNK; c++) {
            size_t off = ((size_t)(h * NCHUNK + c)) * HD * HD + idx;
            float t = g_S[off];
            g_Spre[off] = run;
            run += t;
        }
    }
}

// ---------------- intra-chunk scan + readout + fused L2 norm ----------------
// 256 threads: 4 threads per column e. k/v tiles transposed-filled (stride 68).
__global__ __launch_bounds__(256) void scan_readout_kernel(const float* __restrict__ scale) {
    extern __shared__ float sm[];
    float* qs = sm;                      // 128*68
    float* ks = sm + 128 * 68;
    float* vs = sm + 2 * 128 * 68;
    float* os = sm + 3 * 128 * 68;       // 128*64 output staging
    float* gs = sm + 3 * 128 * 68 + 128 * 64;  // 128
    int hb = blockIdx.x;
    int h = hb >> 4, c = hb & 15;
    int tid = threadIdx.x;               // 256
    int l0 = c * TCH;
    // q: row-major global -> [row][68]
    for (int idx = tid; idx < 2048; idx += 256) {
        int row = idx >> 4, cf = idx & 15;
        *reinterpret_cast<float4*>(&qs[row * 68 + cf * 4]) =
            *reinterpret_cast<const float4*>(g_q + (size_t)(l0 + row) * DMODEL + h * HD + cf * 4);
    }
    fill_tile_T(ks, g_kf, h * HD, l0, tid);
    fill_tile_T(vs, g_vf, h * HD, l0, tid);
    if (tid < TCH) gs[tid] = g_gate[h * LSEQ + l0 + tid];
    int e = tid >> 2, quarter = tid & 3, d0 = quarter * 16;
    float M[16], sc[16];
    {
        const float* Sp = g_Spre + (size_t)hb * HD * HD;
#pragma unroll
        for (int j = 0; j < 16; j++) {
            M[j]  = Sp[(d0 + j) * 64 + e];
            sc[j] = scale[(d0 + j) * 64 + e];
        }
    }
    float G = g_Gpre[h * NCHUNK + c];
    __syncthreads();
    const float4* q4 = reinterpret_cast<const float4*>(qs);
    const float4* v4 = reinterpret_cast<const float4*>(vs);
    int o4 = quarter * 4;
    for (int i = 0; i < TCH; i++) {
        float gg = gs[i]; G += gg;
        float ke = ks[i * 68 + e];
        float gk = gg * ke;
        float r = 0.f;
#pragma unroll
        for (int j4 = 0; j4 < 4; j4++) {
            float4 vv = v4[i * 17 + o4 + j4];
            float4 qq = q4[i * 17 + o4 + j4];
            int jb = j4 * 4;
            M[jb + 0] += gk * vv.x; r += qq.x * (sc[jb + 0] * M[jb + 0]);
            M[jb + 1] += gk * vv.y; r += qq.y * (sc[jb + 1] * M[jb + 1]);
            M[jb + 2] += gk * vv.z; r += qq.z * (sc[jb + 2] * M[jb + 2]);
            M[jb + 3] += gk * vv.w; r += qq.w * (sc[jb + 3] * M[jb + 3]);
        }
        r += __shfl_xor_sync(0xffffffffu, r, 1);
        r += __shfl_xor_sync(0xffffffffu, r, 2);
        if (quarter == 0) os[i * HD + e] = r / fmaxf(G, EPSF);
    }
    __syncthreads();
    // epilogue: per-position L2 norm (identical math to the old spnorm kernel)
    {
        int w = tid >> 5, lane = tid & 31;
        for (int i = w; i < TCH; i += 8) {
            float a = os[i * HD + lane], b = os[i * HD + lane + 32];
            float ss = a * a + b * b;
#pragma unroll
            for (int o = 16; o; o >>= 1) ss += __shfl_xor_sync(0xffffffffu, ss, o);
            float inv = 1.f / fmaxf(sqrtf(ss), EPSF);
            float* outp = g_sraw + (size_t)(l0 + i) * DMODEL + h * HD;
            outp[lane] = a * inv;
            outp[lane + 32] = b * inv;
        }
    }
}
#define SR_SMEM ((3 * 128 * 68 + 128 * 64 + 128) * 4)

// ---------------- launch ----------------
extern "C" void kernel_launch(void* const* d_in, const int* in_sizes, int n_in,
                              void* d_out, int out_size) {
    const float* x     = (const float*)d_in[0];
    const float* sb    = (const float*)d_in[1];
    const float* wq_w  = (const float*)d_in[2];
    const float* wq_b  = (const float*)d_in[3];
    const float* wk_w  = (const float*)d_in[4];
    const float* wk_b  = (const float*)d_in[5];
    const float* wv_w  = (const float*)d_in[6];
    const float* wv_b  = (const float*)d_in[7];
    const float* wo_w  = (const float*)d_in[8];
    const float* wo_b  = (const float*)d_in[9];
    const float* td_w  = (const float*)d_in[10];
    const float* td_b  = (const float*)d_in[11];
    const float* wgz_w = (const float*)d_in[12];
    const float* wgz_b = (const float*)d_in[13];
    const float* kvs   = (const float*)d_in[14];
    float* out = (float*)d_out;

    float* sp;
    cudaGetSymbolAddress((void**)&sp, g_sraw);

    cudaFuncSetAttribute(filtfft_kernel, cudaFuncAttributeMaxDynamicSharedMemorySize, FFT_SMEM);
    cudaFuncSetAttribute(fftconv_kernel, cudaFuncAttributeMaxDynamicSharedMemorySize, FFT_SMEM);
    cudaFuncSetAttribute(gates_kernel, cudaFuncAttributeMaxDynamicSharedMemorySize, GT_SMEM);
    cudaFuncSetAttribute(chunksum_kernel, cudaFuncAttributeMaxDynamicSharedMemorySize, CS_SMEM);
    cudaFuncSetAttribute(scan_readout_kernel, cudaFuncAttributeMaxDynamicSharedMemorySize, SR_SMEM);

    dim3 g4(DMODEL / 64, LSEQ / 64, 4);
    gemm4_kernel<<<g4, 256>>>(x, sb, wq_w, wk_w, wv_w, td_w, wq_b, wk_b, wv_b, td_b);
    filtfft_kernel<<<DMODEL / 2, 256, FFT_SMEM>>>();
    fftconv_kernel<<<DMODEL, 256, FFT_SMEM>>>();
    gates_kernel<<<(NH * LSEQ) / 128, 256, GT_SMEM>>>(wgz_w, wgz_b, kvs);
    chunksum_kernel<<<NH * NCHUNK, 256, CS_SMEM>>>();
    prefix_kernel<<<NH, 512>>>();
    scan_readout_kernel<<<NH * NCHUNK, 256, SR_SMEM>>>(kvs);
    dim3 g1(DMODEL / 64, LSEQ / 64, 1);
    gemm1_kernel<<<g1, 256>>>(sp, wo_w, wo_b, out);
}